// round 8
// baseline (speedup 1.0000x reference)
#include <cuda_runtime.h>
#include <cstdint>

#define BATCH 2
#define SEQ   2048
#define CH    1024
#define NH    16
#define HSZ   64
#define MTOT  (BATCH*SEQ)     // 4096
#define ATTN_SCALE 0.125f
#define SK    40              // GEMM smem row stride (u32); mod32==8 -> LDS.64 conflict-free

// Scratch: device globals (no cudaMalloc allowed)
static __device__ float g_q[(size_t)BATCH*NH*SEQ*HSZ];
static __device__ float g_k[(size_t)BATCH*NH*SEQ*HSZ];
static __device__ float g_v[(size_t)BATCH*NH*SEQ*HSZ];
static __device__ float g_attn[(size_t)MTOT*CH];

static __device__ __forceinline__ uint32_t f2tf32(float v) {
    uint32_t r;
    asm("cvt.rna.tf32.f32 %0, %1;" : "=r"(r) : "f"(v));
    return r;
}

// Pair-permute float4 (cols 4q..4q+3 of an 8-col group) into k-interleaved
// slot order (k0,k4,k1,k5,k2,k6,k3,k7), converting to tf32. Lane pairs (t,t^1)
// hold lower/upper halves of the same group; store address stays row*STRIDE+4q.
static __device__ __forceinline__ uint4 perm_tf32(float4 v, int odd) {
    float s1 = odd ? v.x : v.z;
    float s2 = odd ? v.y : v.w;
    float r1 = __shfl_xor_sync(0xffffffffu, s1, 1);
    float r2 = __shfl_xor_sync(0xffffffffu, s2, 1);
    uint4 o;
    if (odd) { o.x = f2tf32(r1);  o.y = f2tf32(v.z); o.z = f2tf32(r2);  o.w = f2tf32(v.w); }
    else     { o.x = f2tf32(v.x); o.y = f2tf32(r1);  o.z = f2tf32(v.y); o.w = f2tf32(r2);  }
    return o;
}

static __device__ __forceinline__ void mma8(float* c, const uint32_t* a,
                                            uint32_t b0, uint32_t b1) {
    asm volatile(
        "mma.sync.aligned.m16n8k8.row.col.f32.tf32.tf32.f32 "
        "{%0,%1,%2,%3},{%4,%5,%6,%7},{%8,%9},{%0,%1,%2,%3};"
        : "+f"(c[0]), "+f"(c[1]), "+f"(c[2]), "+f"(c[3])
        : "r"(a[0]), "r"(a[1]), "r"(a[2]), "r"(a[3]), "r"(b0), "r"(b1));
}

// ---------------------------------------------------------------------------
// QKV GEMM (tf32 mma.sync): D[128x96] = x[128,1024] . w_qkv^T slice
// ---------------------------------------------------------------------------
#define QKV_SMEM ((2*128*SK + 2*96*SK) * 4)   // 71680 B
__global__ __launch_bounds__(256, 2) void qkv_tc(const float* __restrict__ A,
                                                 const float* __restrict__ W) {
    extern __shared__ __align__(16) float sm[];
    uint32_t* sAu = (uint32_t*)sm;
    uint32_t* sBu = (uint32_t*)sm + 2 * 128 * SK;

    const int tid = threadIdx.x, warp = tid >> 5, lane = tid & 31;
    const int wm = warp >> 1, wn = warp & 1;
    const int g = lane >> 2, t = lane & 3;
    const int odd = tid & 1;
    const int m0 = blockIdx.y * 128;
    const int bx = blockIdx.x;
    const int n0 = bx * 96;

    float acc[2][6][4];
#pragma unroll
    for (int i = 0; i < 2; ++i)
#pragma unroll
        for (int j = 0; j < 6; ++j)
#pragma unroll
            for (int q = 0; q < 4; ++q) acc[i][j][q] = 0.f;

    float4 ar[4], br[3];

    auto LDG = [&](int c) {
        const int k0 = 32 * c;
#pragma unroll
        for (int p = 0; p < 4; ++p) {
            int idx = tid + 256 * p, r = idx >> 3, q = idx & 7;
            ar[p] = *(const float4*)(A + (size_t)(m0 + r) * CH + k0 + 4 * q);
        }
#pragma unroll
        for (int p = 0; p < 3; ++p) {
            int idx = tid + 256 * p, r = idx >> 3, q = idx & 7;
            br[p] = *(const float4*)(W + (size_t)(n0 + r) * CH + k0 + 4 * q);
        }
    };
    auto STS = [&](int buf) {
#pragma unroll
        for (int p = 0; p < 4; ++p) {
            int idx = tid + 256 * p, r = idx >> 3, q = idx & 7;
            *(uint4*)(sAu + buf * 128 * SK + r * SK + 4 * q) = perm_tf32(ar[p], odd);
        }
#pragma unroll
        for (int p = 0; p < 3; ++p) {
            int idx = tid + 256 * p, r = idx >> 3, q = idx & 7;
            *(uint4*)(sBu + buf * 96 * SK + r * SK + 4 * q) = perm_tf32(br[p], odd);
        }
    };

    LDG(0); STS(0); __syncthreads();

    for (int c = 0; c < 32; ++c) {
        const int buf = c & 1;
        if (c < 31) LDG(c + 1);
        const uint32_t* bA = sAu + buf * 128 * SK;
        const uint32_t* bB = sBu + buf * 96 * SK;
#pragma unroll
        for (int s = 0; s < 4; ++s) {
            uint32_t afr[2][4];
#pragma unroll
            for (int mi = 0; mi < 2; ++mi) {
                const uint32_t* pa = bA + (wm * 32 + mi * 16 + g) * SK + s * 8 + 2 * t;
                uint2 lo = *(const uint2*)pa;
                uint2 hi = *(const uint2*)(pa + 8 * SK);
                afr[mi][0] = lo.x; afr[mi][1] = hi.x;
                afr[mi][2] = lo.y; afr[mi][3] = hi.y;
            }
#pragma unroll
            for (int nj = 0; nj < 6; ++nj) {
                uint2 bb = *(const uint2*)(bB + (wn * 48 + nj * 8 + g) * SK + s * 8 + 2 * t);
                mma8(acc[0][nj], afr[0], bb.x, bb.y);
                mma8(acc[1][nj], afr[1], bb.x, bb.y);
            }
        }
        if (c < 31) STS(buf ^ 1);
        __syncthreads();
    }

    float* Ds = sm;
#pragma unroll
    for (int mi = 0; mi < 2; ++mi)
#pragma unroll
        for (int nj = 0; nj < 6; ++nj) {
            int row = wm * 32 + mi * 16 + g;
            int col = wn * 48 + nj * 8 + 2 * t;
            *(float2*)(Ds + row * 100 + col) =
                make_float2(acc[mi][nj][0], acc[mi][nj][1]);
            *(float2*)(Ds + (row + 8) * 100 + col) =
                make_float2(acc[mi][nj][2], acc[mi][nj][3]);
        }
    __syncthreads();

    const int h = bx >> 1, hs0 = (bx & 1) * 32;
#pragma unroll
    for (int p = 0; p < 12; ++p) {
        int id = tid + 256 * p;
        int c4 = id & 7;
        int s = (id >> 3) % 3;
        int row = id / 24;
        int m = m0 + row;
        int bb = m >> 11, nn = m & 2047;
        float* dst = (s == 0) ? g_q : (s == 1) ? g_k : g_v;
        const float* Dr = Ds + row * 100 + 12 * c4 + s;
        float4 o = make_float4(Dr[0], Dr[3], Dr[6], Dr[9]);
        *(float4*)(dst + ((size_t)(bb * NH + h) * SEQ + nn) * HSZ + hs0 + 4 * c4) = o;
    }
}

// ---------------------------------------------------------------------------
// Flash attention (tf32 mma.sync): CTA = 128 query rows x one (b,h).
// Q/K/V stored k-interleaved, stride 72 (64 payload + 8 pad); P plain,
// stride 68 (64 payload + 4 pad; (4g+t) frag banks conflict-free).
// ---------------------------------------------------------------------------
#define ASTR 72
#define PSTR 68
#define ATTN_SMEM ((256*ASTR + 128*PSTR) * 4)   // 108544 B
__global__ __launch_bounds__(256, 2) void attn_tc() {
    extern __shared__ __align__(16) float sm[];
    uint32_t* Qs = (uint32_t*)sm;               // 128 rows, stride ASTR
    uint32_t* Ks = Qs + 128 * ASTR;             // 64 rows
    uint32_t* Vs = Ks + 64 * ASTR;              // 64 rows
    uint32_t* Ps = Vs + 64 * ASTR;              // 128 rows, stride PSTR (plain)

    const int tid = threadIdx.x, warp = tid >> 5, lane = tid & 31;
    const int g = lane >> 2, t = lane & 3;
    const int odd = tid & 1;
    const int pg = 2 * (g & 3) + (g >> 2);      // interleaved slot of col g
    const int bh = blockIdx.y;
    const int m0 = blockIdx.x * 128;
    const int wrow = warp * 16;
    const float* Qg = g_q + (size_t)bh * SEQ * HSZ;
    const float* Kg = g_k + (size_t)bh * SEQ * HSZ;
    const float* Vg = g_v + (size_t)bh * SEQ * HSZ;

    // Load Q tile (scale folded in; x0.125 exact in tf32)
#pragma unroll
    for (int p = 0; p < 8; ++p) {
        int idx = tid + 256 * p;
        int r = idx >> 4, q = idx & 15;
        float4 v = *(const float4*)(Qg + (size_t)(m0 + r) * HSZ + 4 * q);
        v.x *= ATTN_SCALE; v.y *= ATTN_SCALE; v.z *= ATTN_SCALE; v.w *= ATTN_SCALE;
        *(uint4*)(Qs + r * ASTR + 4 * q) = perm_tf32(v, odd);
    }

    float m_i[2] = {-1e30f, -1e30f};
    float l_i[2] = {0.f, 0.f};
    float acc_o[8][4];
#pragma unroll
    for (int nj = 0; nj < 8; ++nj)
#pragma unroll
        for (int q = 0; q < 4; ++q) acc_o[nj][q] = 0.f;

    for (int n0 = 0; n0 < SEQ; n0 += 64) {
        __syncthreads();   // prior iter done reading Ks/Vs (covers Qs on iter 0)
#pragma unroll
        for (int p = 0; p < 4; ++p) {
            int idx = tid + 256 * p;
            int r = idx >> 4, q = idx & 15;
            float4 kv = *(const float4*)(Kg + (size_t)(n0 + r) * HSZ + 4 * q);
            *(uint4*)(Ks + r * ASTR + 4 * q) = perm_tf32(kv, odd);
            float4 vv = *(const float4*)(Vg + (size_t)(n0 + r) * HSZ + 4 * q);
            *(uint4*)(Vs + r * ASTR + 4 * q) = perm_tf32(vv, odd);
        }
        __syncthreads();

        // S = Q.K^T  (warp: 16 x 64)
        float s[8][4];
#pragma unroll
        for (int nj = 0; nj < 8; ++nj)
#pragma unroll
            for (int q = 0; q < 4; ++q) s[nj][q] = 0.f;
#pragma unroll
        for (int ks = 0; ks < 8; ++ks) {
            uint32_t afr[4];
            const uint32_t* pa = Qs + (wrow + g) * ASTR + ks * 8 + 2 * t;
            uint2 lo = *(const uint2*)pa;
            uint2 hi = *(const uint2*)(pa + 8 * ASTR);
            afr[0] = lo.x; afr[1] = hi.x; afr[2] = lo.y; afr[3] = hi.y;
#pragma unroll
            for (int nj = 0; nj < 8; ++nj) {
                uint2 bb = *(const uint2*)(Ks + (nj * 8 + g) * ASTR + ks * 8 + 2 * t);
                mma8(s[nj], afr, bb.x, bb.y);
            }
        }

        // Online softmax on fragment rows (g and g+8)
        float mx0 = -1e30f, mx1 = -1e30f;
#pragma unroll
        for (int nj = 0; nj < 8; ++nj) {
            mx0 = fmaxf(mx0, fmaxf(s[nj][0], s[nj][1]));
            mx1 = fmaxf(mx1, fmaxf(s[nj][2], s[nj][3]));
        }
        mx0 = fmaxf(mx0, __shfl_xor_sync(0xffffffffu, mx0, 1));
        mx0 = fmaxf(mx0, __shfl_xor_sync(0xffffffffu, mx0, 2));
        mx1 = fmaxf(mx1, __shfl_xor_sync(0xffffffffu, mx1, 1));
        mx1 = fmaxf(mx1, __shfl_xor_sync(0xffffffffu, mx1, 2));
        float mn0 = fmaxf(m_i[0], mx0), mn1 = fmaxf(m_i[1], mx1);
        float a0 = __expf(m_i[0] - mn0), a1 = __expf(m_i[1] - mn1);
        m_i[0] = mn0; m_i[1] = mn1;
        float s0 = 0.f, s1 = 0.f;
#pragma unroll
        for (int nj = 0; nj < 8; ++nj) {
            s[nj][0] = __expf(s[nj][0] - mn0);
            s[nj][1] = __expf(s[nj][1] - mn0);
            s[nj][2] = __expf(s[nj][2] - mn1);
            s[nj][3] = __expf(s[nj][3] - mn1);
            s0 += s[nj][0] + s[nj][1];
            s1 += s[nj][2] + s[nj][3];
        }
        s0 += __shfl_xor_sync(0xffffffffu, s0, 1);
        s0 += __shfl_xor_sync(0xffffffffu, s0, 2);
        s1 += __shfl_xor_sync(0xffffffffu, s1, 1);
        s1 += __shfl_xor_sync(0xffffffffu, s1, 2);
        l_i[0] = l_i[0] * a0 + s0;
        l_i[1] = l_i[1] * a1 + s1;
#pragma unroll
        for (int nj = 0; nj < 8; ++nj) {
            acc_o[nj][0] *= a0; acc_o[nj][1] *= a0;
            acc_o[nj][2] *= a1; acc_o[nj][3] *= a1;
        }

        // Stage P (plain layout, per-warp private rows)
        uint32_t* pr0 = Ps + (wrow + g) * PSTR + 2 * t;
        uint32_t* pr1 = Ps + (wrow + g + 8) * PSTR + 2 * t;
#pragma unroll
        for (int nj = 0; nj < 8; ++nj) {
            uint2 w0 = make_uint2(f2tf32(s[nj][0]), f2tf32(s[nj][1]));
            uint2 w1 = make_uint2(f2tf32(s[nj][2]), f2tf32(s[nj][3]));
            *(uint2*)(pr0 + nj * 8) = w0;
            *(uint2*)(pr1 + nj * 8) = w1;
        }
        __syncwarp();

        // O += P.V  (V read transposed via interleaved slot pg -> conflict-free)
#pragma unroll
        for (int ks = 0; ks < 8; ++ks) {
            uint32_t afr[4];
            const uint32_t* pa = Ps + (wrow + g) * PSTR + ks * 8 + t;
            afr[0] = pa[0];
            afr[1] = pa[8 * PSTR];
            afr[2] = pa[4];
            afr[3] = pa[8 * PSTR + 4];
            const uint32_t* vb0 = Vs + (ks * 8 + t) * ASTR + pg;
            const uint32_t* vb1 = Vs + (ks * 8 + t + 4) * ASTR + pg;
#pragma unroll
            for (int nj = 0; nj < 8; ++nj)
                mma8(acc_o[nj], afr, vb0[nj * 8], vb1[nj * 8]);
        }
    }

    // Epilogue: normalize + write (B,N,C) with head offset
    const int b = bh >> 4, h = bh & 15;
    const float inv0 = 1.f / l_i[0], inv1 = 1.f / l_i[1];
    const int r0 = m0 + wrow + g, r1 = r0 + 8;
#pragma unroll
    for (int nj = 0; nj < 8; ++nj) {
        int col = h * HSZ + nj * 8 + 2 * t;
        *(float2*)(g_attn + ((size_t)(b * SEQ + r0)) * CH + col) =
            make_float2(acc_o[nj][0] * inv0, acc_o[nj][1] * inv0);
        *(float2*)(g_attn + ((size_t)(b * SEQ + r1)) * CH + col) =
            make_float2(acc_o[nj][2] * inv1, acc_o[nj][3] * inv1);
    }
}

// ---------------------------------------------------------------------------
// Output projection (tf32 mma.sync): out[128x128] = g_attn . w_out^T + bias
// ---------------------------------------------------------------------------
#define PROJ_SMEM (4*128*SK * 4)   // 81920 B
__global__ __launch_bounds__(256, 2) void proj_tc(const float* __restrict__ W,
                                                  const float* __restrict__ bias,
                                                  float* __restrict__ out) {
    extern __shared__ __align__(16) float sm[];
    uint32_t* sAu = (uint32_t*)sm;
    uint32_t* sBu = (uint32_t*)sm + 2 * 128 * SK;

    const int tid = threadIdx.x, warp = tid >> 5, lane = tid & 31;
    const int wm = warp >> 1, wn = warp & 1;
    const int g = lane >> 2, t = lane & 3;
    const int odd = tid & 1;
    const int m0 = blockIdx.y * 128;
    const int n0 = blockIdx.x * 128;

    float acc[2][8][4];
#pragma unroll
    for (int i = 0; i < 2; ++i)
#pragma unroll
        for (int j = 0; j < 8; ++j)
#pragma unroll
            for (int q = 0; q < 4; ++q) acc[i][j][q] = 0.f;

    float4 ar[4], br[4];

    auto LDG = [&](int c) {
        const int k0 = 32 * c;
#pragma unroll
        for (int p = 0; p < 4; ++p) {
            int idx = tid + 256 * p, r = idx >> 3, q = idx & 7;
            ar[p] = *(const float4*)(g_attn + (size_t)(m0 + r) * CH + k0 + 4 * q);
            br[p] = *(const float4*)(W + (size_t)(n0 + r) * CH + k0 + 4 * q);
        }
    };
    auto STS = [&](int buf) {
#pragma unroll
        for (int p = 0; p < 4; ++p) {
            int idx = tid + 256 * p, r = idx >> 3, q = idx & 7;
            *(uint4*)(sAu + buf * 128 * SK + r * SK + 4 * q) = perm_tf32(ar[p], odd);
            *(uint4*)(sBu + buf * 128 * SK + r * SK + 4 * q) = perm_tf32(br[p], odd);
        }
    };

    LDG(0); STS(0); __syncthreads();

    for (int c = 0; c < 32; ++c) {
        const int buf = c & 1;
        if (c < 31) LDG(c + 1);
        const uint32_t* bA = sAu + buf * 128 * SK;
        const uint32_t* bB = sBu + buf * 128 * SK;
#pragma unroll
        for (int s = 0; s < 4; ++s) {
            uint32_t afr[2][4];
#pragma unroll
            for (int mi = 0; mi < 2; ++mi) {
                const uint32_t* pa = bA + (wm * 32 + mi * 16 + g) * SK + s * 8 + 2 * t;
                uint2 lo = *(const uint2*)pa;
                uint2 hi = *(const uint2*)(pa + 8 * SK);
                afr[mi][0] = lo.x; afr[mi][1] = hi.x;
                afr[mi][2] = lo.y; afr[mi][3] = hi.y;
            }
#pragma unroll
            for (int nj = 0; nj < 8; ++nj) {
                uint2 bb = *(const uint2*)(bB + (wn * 64 + nj * 8 + g) * SK + s * 8 + 2 * t);
                mma8(acc[0][nj], afr[0], bb.x, bb.y);
                mma8(acc[1][nj], afr[1], bb.x, bb.y);
            }
        }
        if (c < 31) STS(buf ^ 1);
        __syncthreads();
    }

#pragma unroll
    for (int mi = 0; mi < 2; ++mi)
#pragma unroll
        for (int nj = 0; nj < 8; ++nj) {
            int row = m0 + wm * 32 + mi * 16 + g;
            int col = n0 + wn * 64 + nj * 8 + 2 * t;
            float b0 = __ldg(bias + col), b1 = __ldg(bias + col + 1);
            *(float2*)(out + (size_t)row * CH + col) =
                make_float2(acc[mi][nj][0] + b0, acc[mi][nj][1] + b1);
            *(float2*)(out + (size_t)(row + 8) * CH + col) =
                make_float2(acc[mi][nj][2] + b0, acc[mi][nj][3] + b1);
        }
}

extern "C" void kernel_launch(void* const* d_in, const int* in_sizes, int n_in,
                              void* d_out, int out_size) {
    const float* x     = (const float*)d_in[0];
    const float* w_qkv = (const float*)d_in[1];
    const float* w_out = (const float*)d_in[2];
    const float* b_out = (const float*)d_in[3];
    float* out = (float*)d_out;

    cudaFuncSetAttribute(qkv_tc, cudaFuncAttributeMaxDynamicSharedMemorySize, QKV_SMEM);
    cudaFuncSetAttribute(attn_tc, cudaFuncAttributeMaxDynamicSharedMemorySize, ATTN_SMEM);
    cudaFuncSetAttribute(proj_tc, cudaFuncAttributeMaxDynamicSharedMemorySize, PROJ_SMEM);

    qkv_tc<<<dim3(32, 32), 256, QKV_SMEM>>>(x, w_qkv);
    attn_tc<<<dim3(SEQ / 128, BATCH * NH), 256, ATTN_SMEM>>>();
    proj_tc<<<dim3(CH / 128, MTOT / 128), 256, PROJ_SMEM>>>(w_out, b_out, out);
}

// round 9
// speedup vs baseline: 1.0960x; 1.0960x over previous
#include <cuda_runtime.h>
#include <cstdint>

#define BATCH 2
#define SEQ   2048
#define CH    1024
#define NH    16
#define HSZ   64
#define MTOT  (BATCH*SEQ)     // 4096
#define ATTN_SCALE 0.125f
#define SK    40              // GEMM smem row stride (u32); mod32==8 -> LDS.64 conflict-free

// Scratch: device globals (no cudaMalloc allowed)
static __device__ float g_q[(size_t)BATCH*NH*SEQ*HSZ];
static __device__ float g_k[(size_t)BATCH*NH*SEQ*HSZ];
static __device__ float g_v[(size_t)BATCH*NH*SEQ*HSZ];
static __device__ float g_attn[(size_t)MTOT*CH];

static __device__ __forceinline__ uint32_t f2tf32(float v) {
    uint32_t r;
    asm("cvt.rna.tf32.f32 %0, %1;" : "=r"(r) : "f"(v));
    return r;
}

// Store one 8-k group (a = k0..k3, b = k4..k7) into interleaved slot order
// (k0,k4,k1,k5)(k2,k6,k3,k7) as two STS.128. No shuffles, no predication.
static __device__ __forceinline__ void ilv_sts(uint32_t* dst, float4 a, float4 b) {
    uint4 lo = make_uint4(f2tf32(a.x), f2tf32(b.x), f2tf32(a.y), f2tf32(b.y));
    uint4 hi = make_uint4(f2tf32(a.z), f2tf32(b.z), f2tf32(a.w), f2tf32(b.w));
    *(uint4*)dst = lo;
    *(uint4*)(dst + 4) = hi;
}

static __device__ __forceinline__ void mma8(float* c, const uint32_t* a,
                                            uint32_t b0, uint32_t b1) {
    asm volatile(
        "mma.sync.aligned.m16n8k8.row.col.f32.tf32.tf32.f32 "
        "{%0,%1,%2,%3},{%4,%5,%6,%7},{%8,%9},{%0,%1,%2,%3};"
        : "+f"(c[0]), "+f"(c[1]), "+f"(c[2]), "+f"(c[3])
        : "r"(a[0]), "r"(a[1]), "r"(a[2]), "r"(a[3]), "r"(b0), "r"(b1));
}

// ---------------------------------------------------------------------------
// QKV GEMM (tf32 mma.sync): D[128x96] = x[128,1024] . w_qkv^T slice
// ---------------------------------------------------------------------------
#define QKV_SMEM ((2*128*SK + 2*96*SK) * 4)   // 71680 B
__global__ __launch_bounds__(256, 2) void qkv_tc(const float* __restrict__ A,
                                                 const float* __restrict__ W) {
    extern __shared__ __align__(16) float sm[];
    uint32_t* sAu = (uint32_t*)sm;
    uint32_t* sBu = (uint32_t*)sm + 2 * 128 * SK;

    const int tid = threadIdx.x, warp = tid >> 5, lane = tid & 31;
    const int wm = warp >> 1, wn = warp & 1;
    const int g = lane >> 2, t = lane & 3;
    const int m0 = blockIdx.y * 128;
    const int bx = blockIdx.x;
    const int n0 = bx * 96;

    float acc[2][6][4];
#pragma unroll
    for (int i = 0; i < 2; ++i)
#pragma unroll
        for (int j = 0; j < 6; ++j)
#pragma unroll
            for (int q = 0; q < 4; ++q) acc[i][j][q] = 0.f;

    float4 ar[4], br[4];

    // A: 512 group-tasks (128 rows x 4 groups of 8k); B: 384 group-tasks.
    auto LDG = [&](int c) {
        const int k0 = 32 * c;
#pragma unroll
        for (int p = 0; p < 2; ++p) {
            int idx = tid + 256 * p, r = idx >> 2, gi = idx & 3;
            const float* src = A + (size_t)(m0 + r) * CH + k0 + 8 * gi;
            ar[2 * p]     = *(const float4*)src;
            ar[2 * p + 1] = *(const float4*)(src + 4);
        }
        {
            int r = tid >> 2, gi = tid & 3;
            const float* src = W + (size_t)(n0 + r) * CH + k0 + 8 * gi;
            br[0] = *(const float4*)src;
            br[1] = *(const float4*)(src + 4);
            if (tid < 128) {
                int idx2 = 256 + tid, r2 = idx2 >> 2, gi2 = idx2 & 3;
                const float* s2 = W + (size_t)(n0 + r2) * CH + k0 + 8 * gi2;
                br[2] = *(const float4*)s2;
                br[3] = *(const float4*)(s2 + 4);
            }
        }
    };
    auto STS = [&](int buf) {
#pragma unroll
        for (int p = 0; p < 2; ++p) {
            int idx = tid + 256 * p, r = idx >> 2, gi = idx & 3;
            ilv_sts(sAu + buf * 128 * SK + r * SK + 8 * gi, ar[2 * p], ar[2 * p + 1]);
        }
        {
            int r = tid >> 2, gi = tid & 3;
            ilv_sts(sBu + buf * 96 * SK + r * SK + 8 * gi, br[0], br[1]);
            if (tid < 128) {
                int idx2 = 256 + tid, r2 = idx2 >> 2, gi2 = idx2 & 3;
                ilv_sts(sBu + buf * 96 * SK + r2 * SK + 8 * gi2, br[2], br[3]);
            }
        }
    };

    LDG(0); STS(0); __syncthreads();

    for (int c = 0; c < 32; ++c) {
        const int buf = c & 1;
        if (c < 31) LDG(c + 1);
        const uint32_t* bA = sAu + buf * 128 * SK;
        const uint32_t* bB = sBu + buf * 96 * SK;
#pragma unroll
        for (int s = 0; s < 4; ++s) {
            uint32_t afr[2][4];
#pragma unroll
            for (int mi = 0; mi < 2; ++mi) {
                const uint32_t* pa = bA + (wm * 32 + mi * 16 + g) * SK + s * 8 + 2 * t;
                uint2 lo = *(const uint2*)pa;
                uint2 hi = *(const uint2*)(pa + 8 * SK);
                afr[mi][0] = lo.x; afr[mi][1] = hi.x;
                afr[mi][2] = lo.y; afr[mi][3] = hi.y;
            }
#pragma unroll
            for (int nj = 0; nj < 6; ++nj) {
                uint2 bb = *(const uint2*)(bB + (wn * 48 + nj * 8 + g) * SK + s * 8 + 2 * t);
                mma8(acc[0][nj], afr[0], bb.x, bb.y);
                mma8(acc[1][nj], afr[1], bb.x, bb.y);
            }
        }
        if (c < 31) STS(buf ^ 1);
        __syncthreads();
    }

    float* Ds = sm;
#pragma unroll
    for (int mi = 0; mi < 2; ++mi)
#pragma unroll
        for (int nj = 0; nj < 6; ++nj) {
            int row = wm * 32 + mi * 16 + g;
            int col = wn * 48 + nj * 8 + 2 * t;
            *(float2*)(Ds + row * 100 + col) =
                make_float2(acc[mi][nj][0], acc[mi][nj][1]);
            *(float2*)(Ds + (row + 8) * 100 + col) =
                make_float2(acc[mi][nj][2], acc[mi][nj][3]);
        }
    __syncthreads();

    const int h = bx >> 1, hs0 = (bx & 1) * 32;
#pragma unroll
    for (int p = 0; p < 12; ++p) {
        int id = tid + 256 * p;
        int c4 = id & 7;
        int s = (id >> 3) % 3;
        int row = id / 24;
        int m = m0 + row;
        int bb = m >> 11, nn = m & 2047;
        float* dst = (s == 0) ? g_q : (s == 1) ? g_k : g_v;
        const float* Dr = Ds + row * 100 + 12 * c4 + s;
        float4 o = make_float4(Dr[0], Dr[3], Dr[6], Dr[9]);
        *(float4*)(dst + ((size_t)(bb * NH + h) * SEQ + nn) * HSZ + hs0 + 4 * c4) = o;
    }
}

// ---------------------------------------------------------------------------
// Flash attention (tf32 mma.sync): CTA = 128 query rows x one (b,h).
// Q/K/V stored k-interleaved, stride 72; P plain, stride 68.
// ---------------------------------------------------------------------------
#define ASTR 72
#define PSTR 68
#define ATTN_SMEM ((256*ASTR + 128*PSTR) * 4)   // 108544 B
__global__ __launch_bounds__(256, 2) void attn_tc() {
    extern __shared__ __align__(16) float sm[];
    uint32_t* Qs = (uint32_t*)sm;               // 128 rows, stride ASTR
    uint32_t* Ks = Qs + 128 * ASTR;             // 64 rows
    uint32_t* Vs = Ks + 64 * ASTR;              // 64 rows
    uint32_t* Ps = Vs + 64 * ASTR;              // 128 rows, stride PSTR (plain)

    const int tid = threadIdx.x, warp = tid >> 5, lane = tid & 31;
    const int g = lane >> 2, t = lane & 3;
    const int pg = 2 * (g & 3) + (g >> 2);      // interleaved slot of col g
    const int bh = blockIdx.y;
    const int m0 = blockIdx.x * 128;
    const int wrow = warp * 16;
    const float* Qg = g_q + (size_t)bh * SEQ * HSZ;
    const float* Kg = g_k + (size_t)bh * SEQ * HSZ;
    const float* Vg = g_v + (size_t)bh * SEQ * HSZ;

    // Load Q tile: 1024 group-tasks (128 rows x 8 groups), scale folded in.
#pragma unroll
    for (int p = 0; p < 4; ++p) {
        int idx = tid + 256 * p, r = idx >> 3, gi = idx & 7;
        const float* src = Qg + (size_t)(m0 + r) * HSZ + 8 * gi;
        float4 a = *(const float4*)src, b = *(const float4*)(src + 4);
        a.x *= ATTN_SCALE; a.y *= ATTN_SCALE; a.z *= ATTN_SCALE; a.w *= ATTN_SCALE;
        b.x *= ATTN_SCALE; b.y *= ATTN_SCALE; b.z *= ATTN_SCALE; b.w *= ATTN_SCALE;
        ilv_sts(Qs + r * ASTR + 8 * gi, a, b);
    }

    float m_i[2] = {-1e30f, -1e30f};
    float l_i[2] = {0.f, 0.f};
    float acc_o[8][4];
#pragma unroll
    for (int nj = 0; nj < 8; ++nj)
#pragma unroll
        for (int q = 0; q < 4; ++q) acc_o[nj][q] = 0.f;

    for (int n0 = 0; n0 < SEQ; n0 += 64) {
        __syncthreads();   // prior iter done reading Ks/Vs (covers Qs on iter 0)
        // K/V tiles: 512 group-tasks each (64 rows x 8 groups)
#pragma unroll
        for (int p = 0; p < 2; ++p) {
            int idx = tid + 256 * p, r = idx >> 3, gi = idx & 7;
            const float* sk = Kg + (size_t)(n0 + r) * HSZ + 8 * gi;
            ilv_sts(Ks + r * ASTR + 8 * gi,
                    *(const float4*)sk, *(const float4*)(sk + 4));
            const float* sv = Vg + (size_t)(n0 + r) * HSZ + 8 * gi;
            ilv_sts(Vs + r * ASTR + 8 * gi,
                    *(const float4*)sv, *(const float4*)(sv + 4));
        }
        __syncthreads();

        // S = Q.K^T  (warp: 16 x 64)
        float s[8][4];
#pragma unroll
        for (int nj = 0; nj < 8; ++nj)
#pragma unroll
            for (int q = 0; q < 4; ++q) s[nj][q] = 0.f;
#pragma unroll
        for (int ks = 0; ks < 8; ++ks) {
            uint32_t afr[4];
            const uint32_t* pa = Qs + (wrow + g) * ASTR + ks * 8 + 2 * t;
            uint2 lo = *(const uint2*)pa;
            uint2 hi = *(const uint2*)(pa + 8 * ASTR);
            afr[0] = lo.x; afr[1] = hi.x; afr[2] = lo.y; afr[3] = hi.y;
#pragma unroll
            for (int nj = 0; nj < 8; ++nj) {
                uint2 bb = *(const uint2*)(Ks + (nj * 8 + g) * ASTR + ks * 8 + 2 * t);
                mma8(s[nj], afr, bb.x, bb.y);
            }
        }

        // Online softmax on fragment rows (g and g+8)
        float mx0 = -1e30f, mx1 = -1e30f;
#pragma unroll
        for (int nj = 0; nj < 8; ++nj) {
            mx0 = fmaxf(mx0, fmaxf(s[nj][0], s[nj][1]));
            mx1 = fmaxf(mx1, fmaxf(s[nj][2], s[nj][3]));
        }
        mx0 = fmaxf(mx0, __shfl_xor_sync(0xffffffffu, mx0, 1));
        mx0 = fmaxf(mx0, __shfl_xor_sync(0xffffffffu, mx0, 2));
        mx1 = fmaxf(mx1, __shfl_xor_sync(0xffffffffu, mx1, 1));
        mx1 = fmaxf(mx1, __shfl_xor_sync(0xffffffffu, mx1, 2));
        float mn0 = fmaxf(m_i[0], mx0), mn1 = fmaxf(m_i[1], mx1);
        float a0 = __expf(m_i[0] - mn0), a1 = __expf(m_i[1] - mn1);
        m_i[0] = mn0; m_i[1] = mn1;
        float s0 = 0.f, s1 = 0.f;
#pragma unroll
        for (int nj = 0; nj < 8; ++nj) {
            s[nj][0] = __expf(s[nj][0] - mn0);
            s[nj][1] = __expf(s[nj][1] - mn0);
            s[nj][2] = __expf(s[nj][2] - mn1);
            s[nj][3] = __expf(s[nj][3] - mn1);
            s0 += s[nj][0] + s[nj][1];
            s1 += s[nj][2] + s[nj][3];
        }
        s0 += __shfl_xor_sync(0xffffffffu, s0, 1);
        s0 += __shfl_xor_sync(0xffffffffu, s0, 2);
        s1 += __shfl_xor_sync(0xffffffffu, s1, 1);
        s1 += __shfl_xor_sync(0xffffffffu, s1, 2);
        l_i[0] = l_i[0] * a0 + s0;
        l_i[1] = l_i[1] * a1 + s1;
#pragma unroll
        for (int nj = 0; nj < 8; ++nj) {
            acc_o[nj][0] *= a0; acc_o[nj][1] *= a0;
            acc_o[nj][2] *= a1; acc_o[nj][3] *= a1;
        }

        // Stage P (plain layout, per-warp private rows)
        uint32_t* pr0 = Ps + (wrow + g) * PSTR + 2 * t;
        uint32_t* pr1 = Ps + (wrow + g + 8) * PSTR + 2 * t;
#pragma unroll
        for (int nj = 0; nj < 8; ++nj) {
            uint2 w0 = make_uint2(f2tf32(s[nj][0]), f2tf32(s[nj][1]));
            uint2 w1 = make_uint2(f2tf32(s[nj][2]), f2tf32(s[nj][3]));
            *(uint2*)(pr0 + nj * 8) = w0;
            *(uint2*)(pr1 + nj * 8) = w1;
        }
        __syncwarp();

        // O += P.V  (V read transposed via interleaved slot pg -> conflict-free)
#pragma unroll
        for (int ks = 0; ks < 8; ++ks) {
            uint32_t afr[4];
            const uint32_t* pa = Ps + (wrow + g) * PSTR + ks * 8 + t;
            afr[0] = pa[0];
            afr[1] = pa[8 * PSTR];
            afr[2] = pa[4];
            afr[3] = pa[8 * PSTR + 4];
            const uint32_t* vb0 = Vs + (ks * 8 + t) * ASTR + pg;
            const uint32_t* vb1 = Vs + (ks * 8 + t + 4) * ASTR + pg;
#pragma unroll
            for (int nj = 0; nj < 8; ++nj)
                mma8(acc_o[nj], afr, vb0[nj * 8], vb1[nj * 8]);
        }
    }

    // Epilogue: normalize + write (B,N,C) with head offset
    const int b = bh >> 4, h = bh & 15;
    const float inv0 = 1.f / l_i[0], inv1 = 1.f / l_i[1];
    const int r0 = m0 + wrow + g, r1 = r0 + 8;
#pragma unroll
    for (int nj = 0; nj < 8; ++nj) {
        int col = h * HSZ + nj * 8 + 2 * t;
        *(float2*)(g_attn + ((size_t)(b * SEQ + r0)) * CH + col) =
            make_float2(acc_o[nj][0] * inv0, acc_o[nj][1] * inv0);
        *(float2*)(g_attn + ((size_t)(b * SEQ + r1)) * CH + col) =
            make_float2(acc_o[nj][2] * inv1, acc_o[nj][3] * inv1);
    }
}

// ---------------------------------------------------------------------------
// Output projection (tf32 mma.sync): out[128x128] = g_attn . w_out^T + bias
// ---------------------------------------------------------------------------
#define PROJ_SMEM (4*128*SK * 4)   // 81920 B
__global__ __launch_bounds__(256, 2) void proj_tc(const float* __restrict__ W,
                                                  const float* __restrict__ bias,
                                                  float* __restrict__ out) {
    extern __shared__ __align__(16) float sm[];
    uint32_t* sAu = (uint32_t*)sm;
    uint32_t* sBu = (uint32_t*)sm + 2 * 128 * SK;

    const int tid = threadIdx.x, warp = tid >> 5, lane = tid & 31;
    const int wm = warp >> 1, wn = warp & 1;
    const int g = lane >> 2, t = lane & 3;
    const int m0 = blockIdx.y * 128;
    const int n0 = blockIdx.x * 128;

    float acc[2][8][4];
#pragma unroll
    for (int i = 0; i < 2; ++i)
#pragma unroll
        for (int j = 0; j < 8; ++j)
#pragma unroll
            for (int q = 0; q < 4; ++q) acc[i][j][q] = 0.f;

    float4 ar[4], br[4];

    auto LDG = [&](int c) {
        const int k0 = 32 * c;
#pragma unroll
        for (int p = 0; p < 2; ++p) {
            int idx = tid + 256 * p, r = idx >> 2, gi = idx & 3;
            const float* sa = g_attn + (size_t)(m0 + r) * CH + k0 + 8 * gi;
            ar[2 * p]     = *(const float4*)sa;
            ar[2 * p + 1] = *(const float4*)(sa + 4);
            const float* sb = W + (size_t)(n0 + r) * CH + k0 + 8 * gi;
            br[2 * p]     = *(const float4*)sb;
            br[2 * p + 1] = *(const float4*)(sb + 4);
        }
    };
    auto STS = [&](int buf) {
#pragma unroll
        for (int p = 0; p < 2; ++p) {
            int idx = tid + 256 * p, r = idx >> 2, gi = idx & 3;
            ilv_sts(sAu + buf * 128 * SK + r * SK + 8 * gi, ar[2 * p], ar[2 * p + 1]);
            ilv_sts(sBu + buf * 128 * SK + r * SK + 8 * gi, br[2 * p], br[2 * p + 1]);
        }
    };

    LDG(0); STS(0); __syncthreads();

    for (int c = 0; c < 32; ++c) {
        const int buf = c & 1;
        if (c < 31) LDG(c + 1);
        const uint32_t* bA = sAu + buf * 128 * SK;
        const uint32_t* bB = sBu + buf * 128 * SK;
#pragma unroll
        for (int s = 0; s < 4; ++s) {
            uint32_t afr[2][4];
#pragma unroll
            for (int mi = 0; mi < 2; ++mi) {
                const uint32_t* pa = bA + (wm * 32 + mi * 16 + g) * SK + s * 8 + 2 * t;
                uint2 lo = *(const uint2*)pa;
                uint2 hi = *(const uint2*)(pa + 8 * SK);
                afr[mi][0] = lo.x; afr[mi][1] = hi.x;
                afr[mi][2] = lo.y; afr[mi][3] = hi.y;
            }
#pragma unroll
            for (int nj = 0; nj < 8; ++nj) {
                uint2 bb = *(const uint2*)(bB + (wn * 64 + nj * 8 + g) * SK + s * 8 + 2 * t);
                mma8(acc[0][nj], afr[0], bb.x, bb.y);
                mma8(acc[1][nj], afr[1], bb.x, bb.y);
            }
        }
        if (c < 31) STS(buf ^ 1);
        __syncthreads();
    }

#pragma unroll
    for (int mi = 0; mi < 2; ++mi)
#pragma unroll
        for (int nj = 0; nj < 8; ++nj) {
            int row = m0 + wm * 32 + mi * 16 + g;
            int col = n0 + wn * 64 + nj * 8 + 2 * t;
            float b0 = __ldg(bias + col), b1 = __ldg(bias + col + 1);
            *(float2*)(out + (size_t)row * CH + col) =
                make_float2(acc[mi][nj][0] + b0, acc[mi][nj][1] + b1);
            *(float2*)(out + (size_t)(row + 8) * CH + col) =
                make_float2(acc[mi][nj][2] + b0, acc[mi][nj][3] + b1);
        }
}

extern "C" void kernel_launch(void* const* d_in, const int* in_sizes, int n_in,
                              void* d_out, int out_size) {
    const float* x     = (const float*)d_in[0];
    const float* w_qkv = (const float*)d_in[1];
    const float* w_out = (const float*)d_in[2];
    const float* b_out = (const float*)d_in[3];
    float* out = (float*)d_out;

    cudaFuncSetAttribute(qkv_tc, cudaFuncAttributeMaxDynamicSharedMemorySize, QKV_SMEM);
    cudaFuncSetAttribute(attn_tc, cudaFuncAttributeMaxDynamicSharedMemorySize, ATTN_SMEM);
    cudaFuncSetAttribute(proj_tc, cudaFuncAttributeMaxDynamicSharedMemorySize, PROJ_SMEM);

    qkv_tc<<<dim3(32, 32), 256, QKV_SMEM>>>(x, w_qkv);
    attn_tc<<<dim3(SEQ / 128, BATCH * NH), 256, ATTN_SMEM>>>();
    proj_tc<<<dim3(CH / 128, MTOT / 128), 256, PROJ_SMEM>>>(w_out, b_out, out);
}

// round 10
// speedup vs baseline: 1.2320x; 1.1240x over previous
#include <cuda_runtime.h>
#include <cstdint>

#define BATCH 2
#define SEQ   2048
#define CH    1024
#define NH    16
#define HSZ   64
#define MTOT  (BATCH*SEQ)     // 4096
#define ATTN_SCALE 0.125f
#define SK    36              // smem row stride (floats) -> conflict-free frags

// Scratch: device globals (no cudaMalloc allowed)
static __device__ float g_q[(size_t)BATCH*NH*SEQ*HSZ];
static __device__ float g_k[(size_t)BATCH*NH*SEQ*HSZ];
static __device__ float g_v[(size_t)BATCH*NH*SEQ*HSZ];
static __device__ float g_attn[(size_t)MTOT*CH];

static __device__ __forceinline__ uint32_t f2tf32(float v) {
    uint32_t r;
    asm("cvt.rna.tf32.f32 %0, %1;" : "=r"(r) : "f"(v));
    return r;
}

static __device__ __forceinline__ void mma8(float* c, const uint32_t* a,
                                            uint32_t b0, uint32_t b1) {
    asm volatile(
        "mma.sync.aligned.m16n8k8.row.col.f32.tf32.tf32.f32 "
        "{%0,%1,%2,%3},{%4,%5,%6,%7},{%8,%9},{%0,%1,%2,%3};"
        : "+f"(c[0]), "+f"(c[1]), "+f"(c[2]), "+f"(c[3])
        : "r"(a[0]), "r"(a[1]), "r"(a[2]), "r"(a[3]), "r"(b0), "r"(b1));
}

// ---------------------------------------------------------------------------
// QKV GEMM (tf32 mma.sync): D[128x96] = x[128,1024] . w_qkv^T slice
// (round-4 verified version, 190 us)
// ---------------------------------------------------------------------------
#define QKV_SMEM ((2*128*SK + 2*96*SK) * 4)   // 64512 B
__global__ __launch_bounds__(256, 2) void qkv_tc(const float* __restrict__ A,
                                                 const float* __restrict__ W) {
    extern __shared__ __align__(16) float sm[];
    uint32_t* sAu = (uint32_t*)sm;
    uint32_t* sBu = (uint32_t*)sm + 2 * 128 * SK;

    const int tid = threadIdx.x, warp = tid >> 5, lane = tid & 31;
    const int wm = warp >> 1, wn = warp & 1;
    const int g = lane >> 2, t = lane & 3;
    const int m0 = blockIdx.y * 128;
    const int bx = blockIdx.x;
    const int n0 = bx * 96;

    float acc[2][6][4];
#pragma unroll
    for (int i = 0; i < 2; ++i)
#pragma unroll
        for (int j = 0; j < 6; ++j)
#pragma unroll
            for (int q = 0; q < 4; ++q) acc[i][j][q] = 0.f;

    float4 ar[4], br[3];

    auto LDG = [&](int c) {
        const int k0 = 32 * c;
#pragma unroll
        for (int p = 0; p < 4; ++p) {
            int idx = tid + 256 * p, r = idx >> 3, q = idx & 7;
            ar[p] = *(const float4*)(A + (size_t)(m0 + r) * CH + k0 + 4 * q);
        }
#pragma unroll
        for (int p = 0; p < 3; ++p) {
            int idx = tid + 256 * p, r = idx >> 3, q = idx & 7;
            br[p] = *(const float4*)(W + (size_t)(n0 + r) * CH + k0 + 4 * q);
        }
    };
    auto STS = [&](int buf) {
#pragma unroll
        for (int p = 0; p < 4; ++p) {
            int idx = tid + 256 * p, r = idx >> 3, q = idx & 7;
            uint32_t* d = sAu + buf * 128 * SK + r * SK + 4 * q;
            d[0] = f2tf32(ar[p].x); d[1] = f2tf32(ar[p].y);
            d[2] = f2tf32(ar[p].z); d[3] = f2tf32(ar[p].w);
        }
#pragma unroll
        for (int p = 0; p < 3; ++p) {
            int idx = tid + 256 * p, r = idx >> 3, q = idx & 7;
            uint32_t* d = sBu + buf * 96 * SK + r * SK + 4 * q;
            d[0] = f2tf32(br[p].x); d[1] = f2tf32(br[p].y);
            d[2] = f2tf32(br[p].z); d[3] = f2tf32(br[p].w);
        }
    };

    LDG(0); STS(0); __syncthreads();

    for (int c = 0; c < 32; ++c) {
        const int buf = c & 1;
        if (c < 31) LDG(c + 1);
        const uint32_t* bA = sAu + buf * 128 * SK;
        const uint32_t* bB = sBu + buf * 96 * SK;
#pragma unroll
        for (int s = 0; s < 4; ++s) {
            uint32_t afr[2][4];
#pragma unroll
            for (int mi = 0; mi < 2; ++mi) {
                const uint32_t* pa = bA + (wm * 32 + mi * 16 + g) * SK + s * 8 + t;
                afr[mi][0] = pa[0];
                afr[mi][1] = pa[8 * SK];
                afr[mi][2] = pa[4];
                afr[mi][3] = pa[8 * SK + 4];
            }
#pragma unroll
            for (int nj = 0; nj < 6; ++nj) {
                const uint32_t* pb = bB + (wn * 48 + nj * 8 + g) * SK + s * 8 + t;
                uint32_t b0 = pb[0], b1 = pb[4];
                mma8(acc[0][nj], afr[0], b0, b1);
                mma8(acc[1][nj], afr[1], b0, b1);
            }
        }
        if (c < 31) STS(buf ^ 1);
        __syncthreads();
    }

    float* Ds = sm;
#pragma unroll
    for (int mi = 0; mi < 2; ++mi)
#pragma unroll
        for (int nj = 0; nj < 6; ++nj) {
            int row = wm * 32 + mi * 16 + g;
            int col = wn * 48 + nj * 8 + 2 * t;
            *(float2*)(Ds + row * 100 + col) =
                make_float2(acc[mi][nj][0], acc[mi][nj][1]);
            *(float2*)(Ds + (row + 8) * 100 + col) =
                make_float2(acc[mi][nj][2], acc[mi][nj][3]);
        }
    __syncthreads();

    const int h = bx >> 1, hs0 = (bx & 1) * 32;
#pragma unroll
    for (int p = 0; p < 12; ++p) {
        int id = tid + 256 * p;
        int c4 = id & 7;
        int s = (id >> 3) % 3;
        int row = id / 24;
        int m = m0 + row;
        int bb = m >> 11, nn = m & 2047;
        float* dst = (s == 0) ? g_q : (s == 1) ? g_k : g_v;
        const float* Dr = Ds + row * 100 + 12 * c4 + s;
        float4 o = make_float4(Dr[0], Dr[3], Dr[6], Dr[9]);
        *(float4*)(dst + ((size_t)(bb * NH + h) * SEQ + nn) * HSZ + hs0 + 4 * c4) = o;
    }
}

// ---------------------------------------------------------------------------
// Flash attention (tf32 mma.sync): CTA = 128 query rows x one (b,h).
// Q fragments hoisted into registers (loaded once from gmem).
// K/V/P in smem, plain stride-68 layout (round-4 verified geometry).
// ---------------------------------------------------------------------------
#define ASTR 68
#define ATTN_SMEM (256 * ASTR * 4)   // 69632 B  (K 64 + V 64 + P 128 rows)
__global__ __launch_bounds__(256, 2) void attn_tc() {
    extern __shared__ __align__(16) float sm[];
    uint32_t* Ks = (uint32_t*)sm;               // [64][ASTR]
    uint32_t* Vs = Ks + 64 * ASTR;              // [64][ASTR]
    uint32_t* Ps = Vs + 64 * ASTR;              // [128][ASTR]

    const int tid = threadIdx.x, warp = tid >> 5, lane = tid & 31;
    const int g = lane >> 2, t = lane & 3;
    const int bh = blockIdx.y;
    const int m0 = blockIdx.x * 128;
    const int wrow = warp * 16;
    const float* Qg = g_q + (size_t)bh * SEQ * HSZ;
    const float* Kg = g_k + (size_t)bh * SEQ * HSZ;
    const float* Vg = g_v + (size_t)bh * SEQ * HSZ;

    // Hoist Q A-fragments into registers (scale folded; x0.125 exact in tf32)
    uint32_t qfr[8][4];
    {
        const float* q0 = Qg + (size_t)(m0 + wrow + g) * HSZ;
        const float* q1 = Qg + (size_t)(m0 + wrow + g + 8) * HSZ;
#pragma unroll
        for (int ks = 0; ks < 8; ++ks) {
            int c0 = ks * 8 + t, c1 = c0 + 4;
            qfr[ks][0] = f2tf32(q0[c0] * ATTN_SCALE);
            qfr[ks][1] = f2tf32(q1[c0] * ATTN_SCALE);
            qfr[ks][2] = f2tf32(q0[c1] * ATTN_SCALE);
            qfr[ks][3] = f2tf32(q1[c1] * ATTN_SCALE);
        }
    }

    float m_i[2] = {-1e30f, -1e30f};
    float l_i[2] = {0.f, 0.f};
    float acc_o[8][4];
#pragma unroll
    for (int nj = 0; nj < 8; ++nj)
#pragma unroll
        for (int q = 0; q < 4; ++q) acc_o[nj][q] = 0.f;

    for (int n0 = 0; n0 < SEQ; n0 += 64) {
        __syncthreads();   // prior iter done reading Ks/Vs/Ps
#pragma unroll
        for (int p = 0; p < 4; ++p) {
            int idx = tid + 256 * p;
            int r = idx >> 4, q = idx & 15;
            float4 kv = *(const float4*)(Kg + (size_t)(n0 + r) * HSZ + 4 * q);
            *(uint4*)(Ks + r * ASTR + 4 * q) =
                make_uint4(f2tf32(kv.x), f2tf32(kv.y), f2tf32(kv.z), f2tf32(kv.w));
            float4 vv = *(const float4*)(Vg + (size_t)(n0 + r) * HSZ + 4 * q);
            *(uint4*)(Vs + r * ASTR + 4 * q) =
                make_uint4(f2tf32(vv.x), f2tf32(vv.y), f2tf32(vv.z), f2tf32(vv.w));
        }
        __syncthreads();

        // S = Q.K^T  (warp: 16 x 64); Q fragments already in registers
        float s[8][4];
#pragma unroll
        for (int nj = 0; nj < 8; ++nj)
#pragma unroll
            for (int q = 0; q < 4; ++q) s[nj][q] = 0.f;
#pragma unroll
        for (int ks = 0; ks < 8; ++ks) {
#pragma unroll
            for (int nj = 0; nj < 8; ++nj) {
                const uint32_t* pb = Ks + (nj * 8 + g) * ASTR + ks * 8 + t;
                mma8(s[nj], qfr[ks], pb[0], pb[4]);
            }
        }

        // Online softmax on fragment rows (g and g+8)
        float mx0 = -1e30f, mx1 = -1e30f;
#pragma unroll
        for (int nj = 0; nj < 8; ++nj) {
            mx0 = fmaxf(mx0, fmaxf(s[nj][0], s[nj][1]));
            mx1 = fmaxf(mx1, fmaxf(s[nj][2], s[nj][3]));
        }
        mx0 = fmaxf(mx0, __shfl_xor_sync(0xffffffffu, mx0, 1));
        mx0 = fmaxf(mx0, __shfl_xor_sync(0xffffffffu, mx0, 2));
        mx1 = fmaxf(mx1, __shfl_xor_sync(0xffffffffu, mx1, 1));
        mx1 = fmaxf(mx1, __shfl_xor_sync(0xffffffffu, mx1, 2));
        float mn0 = fmaxf(m_i[0], mx0), mn1 = fmaxf(m_i[1], mx1);
        float a0 = __expf(m_i[0] - mn0), a1 = __expf(m_i[1] - mn1);
        m_i[0] = mn0; m_i[1] = mn1;
        float s0 = 0.f, s1 = 0.f;
#pragma unroll
        for (int nj = 0; nj < 8; ++nj) {
            s[nj][0] = __expf(s[nj][0] - mn0);
            s[nj][1] = __expf(s[nj][1] - mn0);
            s[nj][2] = __expf(s[nj][2] - mn1);
            s[nj][3] = __expf(s[nj][3] - mn1);
            s0 += s[nj][0] + s[nj][1];
            s1 += s[nj][2] + s[nj][3];
        }
        s0 += __shfl_xor_sync(0xffffffffu, s0, 1);
        s0 += __shfl_xor_sync(0xffffffffu, s0, 2);
        s1 += __shfl_xor_sync(0xffffffffu, s1, 1);
        s1 += __shfl_xor_sync(0xffffffffu, s1, 2);
        l_i[0] = l_i[0] * a0 + s0;
        l_i[1] = l_i[1] * a1 + s1;
#pragma unroll
        for (int nj = 0; nj < 8; ++nj) {
            acc_o[nj][0] *= a0; acc_o[nj][1] *= a0;
            acc_o[nj][2] *= a1; acc_o[nj][3] *= a1;
        }

        // Stage P (per-warp private rows -> only warp-level sync needed)
        uint32_t* pr0 = Ps + (wrow + g) * ASTR + 2 * t;
        uint32_t* pr1 = Ps + (wrow + g + 8) * ASTR + 2 * t;
#pragma unroll
        for (int nj = 0; nj < 8; ++nj) {
            uint2 w0 = make_uint2(f2tf32(s[nj][0]), f2tf32(s[nj][1]));
            uint2 w1 = make_uint2(f2tf32(s[nj][2]), f2tf32(s[nj][3]));
            *(uint2*)(pr0 + nj * 8) = w0;
            *(uint2*)(pr1 + nj * 8) = w1;
        }
        __syncwarp();

        // O += P.V  (B-frag = transposed read of natural V tile)
#pragma unroll
        for (int ks = 0; ks < 8; ++ks) {
            uint32_t afr[4];
            const uint32_t* pa = Ps + (wrow + g) * ASTR + ks * 8 + t;
            afr[0] = pa[0];
            afr[1] = pa[8 * ASTR];
            afr[2] = pa[4];
            afr[3] = pa[8 * ASTR + 4];
            const uint32_t* vb0 = Vs + (ks * 8 + t) * ASTR + g;
            const uint32_t* vb1 = Vs + (ks * 8 + t + 4) * ASTR + g;
#pragma unroll
            for (int nj = 0; nj < 8; ++nj)
                mma8(acc_o[nj], afr, vb0[nj * 8], vb1[nj * 8]);
        }
    }

    // Epilogue: normalize + write (B,N,C) with head offset
    const int b = bh >> 4, h = bh & 15;
    const float inv0 = 1.f / l_i[0], inv1 = 1.f / l_i[1];
    const int r0 = m0 + wrow + g, r1 = r0 + 8;
#pragma unroll
    for (int nj = 0; nj < 8; ++nj) {
        int col = h * HSZ + nj * 8 + 2 * t;
        *(float2*)(g_attn + ((size_t)(b * SEQ + r0)) * CH + col) =
            make_float2(acc_o[nj][0] * inv0, acc_o[nj][1] * inv0);
        *(float2*)(g_attn + ((size_t)(b * SEQ + r1)) * CH + col) =
            make_float2(acc_o[nj][2] * inv1, acc_o[nj][3] * inv1);
    }
}

// ---------------------------------------------------------------------------
// Output projection (tf32 mma.sync): out[128x128] = g_attn . w_out^T + bias
// (round-4 verified version)
// ---------------------------------------------------------------------------
#define PROJ_SMEM (4*128*SK * 4)   // 73728 B
__global__ __launch_bounds__(256, 2) void proj_tc(const float* __restrict__ W,
                                                  const float* __restrict__ bias,
                                                  float* __restrict__ out) {
    extern __shared__ __align__(16) float sm[];
    uint32_t* sAu = (uint32_t*)sm;
    uint32_t* sBu = (uint32_t*)sm + 2 * 128 * SK;

    const int tid = threadIdx.x, warp = tid >> 5, lane = tid & 31;
    const int wm = warp >> 1, wn = warp & 1;
    const int g = lane >> 2, t = lane & 3;
    const int m0 = blockIdx.y * 128;
    const int n0 = blockIdx.x * 128;

    float acc[2][8][4];
#pragma unroll
    for (int i = 0; i < 2; ++i)
#pragma unroll
        for (int j = 0; j < 8; ++j)
#pragma unroll
            for (int q = 0; q < 4; ++q) acc[i][j][q] = 0.f;

    float4 ar[4], br[4];

    auto LDG = [&](int c) {
        const int k0 = 32 * c;
#pragma unroll
        for (int p = 0; p < 4; ++p) {
            int idx = tid + 256 * p, r = idx >> 3, q = idx & 7;
            ar[p] = *(const float4*)(g_attn + (size_t)(m0 + r) * CH + k0 + 4 * q);
            br[p] = *(const float4*)(W + (size_t)(n0 + r) * CH + k0 + 4 * q);
        }
    };
    auto STS = [&](int buf) {
#pragma unroll
        for (int p = 0; p < 4; ++p) {
            int idx = tid + 256 * p, r = idx >> 3, q = idx & 7;
            uint32_t* dA = sAu + buf * 128 * SK + r * SK + 4 * q;
            dA[0] = f2tf32(ar[p].x); dA[1] = f2tf32(ar[p].y);
            dA[2] = f2tf32(ar[p].z); dA[3] = f2tf32(ar[p].w);
            uint32_t* dB = sBu + buf * 128 * SK + r * SK + 4 * q;
            dB[0] = f2tf32(br[p].x); dB[1] = f2tf32(br[p].y);
            dB[2] = f2tf32(br[p].z); dB[3] = f2tf32(br[p].w);
        }
    };

    LDG(0); STS(0); __syncthreads();

    for (int c = 0; c < 32; ++c) {
        const int buf = c & 1;
        if (c < 31) LDG(c + 1);
        const uint32_t* bA = sAu + buf * 128 * SK;
        const uint32_t* bB = sBu + buf * 128 * SK;
#pragma unroll
        for (int s = 0; s < 4; ++s) {
            uint32_t afr[2][4];
#pragma unroll
            for (int mi = 0; mi < 2; ++mi) {
                const uint32_t* pa = bA + (wm * 32 + mi * 16 + g) * SK + s * 8 + t;
                afr[mi][0] = pa[0];
                afr[mi][1] = pa[8 * SK];
                afr[mi][2] = pa[4];
                afr[mi][3] = pa[8 * SK + 4];
            }
#pragma unroll
            for (int nj = 0; nj < 8; ++nj) {
                const uint32_t* pb = bB + (wn * 64 + nj * 8 + g) * SK + s * 8 + t;
                uint32_t b0 = pb[0], b1 = pb[4];
                mma8(acc[0][nj], afr[0], b0, b1);
                mma8(acc[1][nj], afr[1], b0, b1);
            }
        }
        if (c < 31) STS(buf ^ 1);
        __syncthreads();
    }

#pragma unroll
    for (int mi = 0; mi < 2; ++mi)
#pragma unroll
        for (int nj = 0; nj < 8; ++nj) {
            int row = m0 + wm * 32 + mi * 16 + g;
            int col = n0 + wn * 64 + nj * 8 + 2 * t;
            float b0 = __ldg(bias + col), b1 = __ldg(bias + col + 1);
            *(float2*)(out + (size_t)row * CH + col) =
                make_float2(acc[mi][nj][0] + b0, acc[mi][nj][1] + b1);
            *(float2*)(out + (size_t)(row + 8) * CH + col) =
                make_float2(acc[mi][nj][2] + b0, acc[mi][nj][3] + b1);
        }
}

extern "C" void kernel_launch(void* const* d_in, const int* in_sizes, int n_in,
                              void* d_out, int out_size) {
    const float* x     = (const float*)d_in[0];
    const float* w_qkv = (const float*)d_in[1];
    const float* w_out = (const float*)d_in[2];
    const float* b_out = (const float*)d_in[3];
    float* out = (float*)d_out;

    cudaFuncSetAttribute(qkv_tc, cudaFuncAttributeMaxDynamicSharedMemorySize, QKV_SMEM);
    cudaFuncSetAttribute(attn_tc, cudaFuncAttributeMaxDynamicSharedMemorySize, ATTN_SMEM);
    cudaFuncSetAttribute(proj_tc, cudaFuncAttributeMaxDynamicSharedMemorySize, PROJ_SMEM);

    qkv_tc<<<dim3(32, 32), 256, QKV_SMEM>>>(x, w_qkv);
    attn_tc<<<dim3(SEQ / 128, BATCH * NH), 256, ATTN_SMEM>>>();
    proj_tc<<<dim3(CH / 128, MTOT / 128), 256, PROJ_SMEM>>>(w_out, b_out, out);
}

// round 11
// speedup vs baseline: 1.2538x; 1.0177x over previous
#include <cuda_runtime.h>
#include <cstdint>

#define BATCH 2
#define SEQ   2048
#define CH    1024
#define NH    16
#define HSZ   64
#define MTOT  (BATCH*SEQ)     // 4096
#define QSCALE 0.18033688011112042f   // 0.125 * log2(e): softmax in log2 domain
#define SK    36              // smem row stride (floats) -> conflict-free frags

// Scratch: device globals (no cudaMalloc allowed)
static __device__ float g_q[(size_t)BATCH*NH*SEQ*HSZ];
static __device__ float g_k[(size_t)BATCH*NH*SEQ*HSZ];
static __device__ float g_v[(size_t)BATCH*NH*SEQ*HSZ];
static __device__ float g_attn[(size_t)MTOT*CH];

static __device__ __forceinline__ uint32_t f2tf32(float v) {
    uint32_t r;
    asm("cvt.rna.tf32.f32 %0, %1;" : "=r"(r) : "f"(v));
    return r;
}

static __device__ __forceinline__ void mma8(float* c, const uint32_t* a,
                                            uint32_t b0, uint32_t b1) {
    asm volatile(
        "mma.sync.aligned.m16n8k8.row.col.f32.tf32.tf32.f32 "
        "{%0,%1,%2,%3},{%4,%5,%6,%7},{%8,%9},{%0,%1,%2,%3};"
        : "+f"(c[0]), "+f"(c[1]), "+f"(c[2]), "+f"(c[3])
        : "r"(a[0]), "r"(a[1]), "r"(a[2]), "r"(a[3]), "r"(b0), "r"(b1));
}

// ---------------------------------------------------------------------------
// QKV GEMM (tf32 mma.sync): D[128x96] = x[128,1024] . w_qkv^T slice
// (round-4 verified version, 190 us)
// ---------------------------------------------------------------------------
#define QKV_SMEM ((2*128*SK + 2*96*SK) * 4)   // 64512 B
__global__ __launch_bounds__(256, 2) void qkv_tc(const float* __restrict__ A,
                                                 const float* __restrict__ W) {
    extern __shared__ __align__(16) float sm[];
    uint32_t* sAu = (uint32_t*)sm;
    uint32_t* sBu = (uint32_t*)sm + 2 * 128 * SK;

    const int tid = threadIdx.x, warp = tid >> 5, lane = tid & 31;
    const int wm = warp >> 1, wn = warp & 1;
    const int g = lane >> 2, t = lane & 3;
    const int m0 = blockIdx.y * 128;
    const int bx = blockIdx.x;
    const int n0 = bx * 96;

    float acc[2][6][4];
#pragma unroll
    for (int i = 0; i < 2; ++i)
#pragma unroll
        for (int j = 0; j < 6; ++j)
#pragma unroll
            for (int q = 0; q < 4; ++q) acc[i][j][q] = 0.f;

    float4 ar[4], br[3];

    auto LDG = [&](int c) {
        const int k0 = 32 * c;
#pragma unroll
        for (int p = 0; p < 4; ++p) {
            int idx = tid + 256 * p, r = idx >> 3, q = idx & 7;
            ar[p] = *(const float4*)(A + (size_t)(m0 + r) * CH + k0 + 4 * q);
        }
#pragma unroll
        for (int p = 0; p < 3; ++p) {
            int idx = tid + 256 * p, r = idx >> 3, q = idx & 7;
            br[p] = *(const float4*)(W + (size_t)(n0 + r) * CH + k0 + 4 * q);
        }
    };
    auto STS = [&](int buf) {
#pragma unroll
        for (int p = 0; p < 4; ++p) {
            int idx = tid + 256 * p, r = idx >> 3, q = idx & 7;
            uint32_t* d = sAu + buf * 128 * SK + r * SK + 4 * q;
            d[0] = f2tf32(ar[p].x); d[1] = f2tf32(ar[p].y);
            d[2] = f2tf32(ar[p].z); d[3] = f2tf32(ar[p].w);
        }
#pragma unroll
        for (int p = 0; p < 3; ++p) {
            int idx = tid + 256 * p, r = idx >> 3, q = idx & 7;
            uint32_t* d = sBu + buf * 96 * SK + r * SK + 4 * q;
            d[0] = f2tf32(br[p].x); d[1] = f2tf32(br[p].y);
            d[2] = f2tf32(br[p].z); d[3] = f2tf32(br[p].w);
        }
    };

    LDG(0); STS(0); __syncthreads();

    for (int c = 0; c < 32; ++c) {
        const int buf = c & 1;
        if (c < 31) LDG(c + 1);
        const uint32_t* bA = sAu + buf * 128 * SK;
        const uint32_t* bB = sBu + buf * 96 * SK;
#pragma unroll
        for (int s = 0; s < 4; ++s) {
            uint32_t afr[2][4];
#pragma unroll
            for (int mi = 0; mi < 2; ++mi) {
                const uint32_t* pa = bA + (wm * 32 + mi * 16 + g) * SK + s * 8 + t;
                afr[mi][0] = pa[0];
                afr[mi][1] = pa[8 * SK];
                afr[mi][2] = pa[4];
                afr[mi][3] = pa[8 * SK + 4];
            }
#pragma unroll
            for (int nj = 0; nj < 6; ++nj) {
                const uint32_t* pb = bB + (wn * 48 + nj * 8 + g) * SK + s * 8 + t;
                uint32_t b0 = pb[0], b1 = pb[4];
                mma8(acc[0][nj], afr[0], b0, b1);
                mma8(acc[1][nj], afr[1], b0, b1);
            }
        }
        if (c < 31) STS(buf ^ 1);
        __syncthreads();
    }

    float* Ds = sm;
#pragma unroll
    for (int mi = 0; mi < 2; ++mi)
#pragma unroll
        for (int nj = 0; nj < 6; ++nj) {
            int row = wm * 32 + mi * 16 + g;
            int col = wn * 48 + nj * 8 + 2 * t;
            *(float2*)(Ds + row * 100 + col) =
                make_float2(acc[mi][nj][0], acc[mi][nj][1]);
            *(float2*)(Ds + (row + 8) * 100 + col) =
                make_float2(acc[mi][nj][2], acc[mi][nj][3]);
        }
    __syncthreads();

    const int h = bx >> 1, hs0 = (bx & 1) * 32;
#pragma unroll
    for (int p = 0; p < 12; ++p) {
        int id = tid + 256 * p;
        int c4 = id & 7;
        int s = (id >> 3) % 3;
        int row = id / 24;
        int m = m0 + row;
        int bb = m >> 11, nn = m & 2047;
        float* dst = (s == 0) ? g_q : (s == 1) ? g_k : g_v;
        const float* Dr = Ds + row * 100 + 12 * c4 + s;
        float4 o = make_float4(Dr[0], Dr[3], Dr[6], Dr[9]);
        *(float4*)(dst + ((size_t)(bb * NH + h) * SEQ + nn) * HSZ + hs0 + 4 * c4) = o;
    }
}

// ---------------------------------------------------------------------------
// Flash attention (tf32 mma.sync): CTA = 128 query rows x one (b,h).
// Q fragments hoisted in registers. 128-key staging tile processed as two
// 64-key halves with no CTA barrier between halves. log2-domain softmax.
// ---------------------------------------------------------------------------
#define ASTR 68
#define ATTN_SMEM (384 * ASTR * 4)   // 104448 B (K 128 + V 128 + P 128 rows)
__global__ __launch_bounds__(256, 2) void attn_tc() {
    extern __shared__ __align__(16) float sm[];
    uint32_t* Ks = (uint32_t*)sm;               // [128][ASTR]
    uint32_t* Vs = Ks + 128 * ASTR;             // [128][ASTR]
    uint32_t* Ps = Vs + 128 * ASTR;             // [128][ASTR]

    const int tid = threadIdx.x, warp = tid >> 5, lane = tid & 31;
    const int g = lane >> 2, t = lane & 3;
    const int bh = blockIdx.y;
    const int m0 = blockIdx.x * 128;
    const int wrow = warp * 16;
    const float* Qg = g_q + (size_t)bh * SEQ * HSZ;
    const float* Kg = g_k + (size_t)bh * SEQ * HSZ;
    const float* Vg = g_v + (size_t)bh * SEQ * HSZ;

    // Hoist Q A-fragments into registers (log2e * 0.125 folded in)
    uint32_t qfr[8][4];
    {
        const float* q0 = Qg + (size_t)(m0 + wrow + g) * HSZ;
        const float* q1 = Qg + (size_t)(m0 + wrow + g + 8) * HSZ;
#pragma unroll
        for (int ks = 0; ks < 8; ++ks) {
            int c0 = ks * 8 + t, c1 = c0 + 4;
            qfr[ks][0] = f2tf32(q0[c0] * QSCALE);
            qfr[ks][1] = f2tf32(q1[c0] * QSCALE);
            qfr[ks][2] = f2tf32(q0[c1] * QSCALE);
            qfr[ks][3] = f2tf32(q1[c1] * QSCALE);
        }
    }

    float m_i[2] = {-1e30f, -1e30f};
    float l_i[2] = {0.f, 0.f};
    float acc_o[8][4];
#pragma unroll
    for (int nj = 0; nj < 8; ++nj)
#pragma unroll
        for (int q = 0; q < 4; ++q) acc_o[nj][q] = 0.f;

    for (int n0 = 0; n0 < SEQ; n0 += 128) {
        __syncthreads();   // all warps done with prior Ks/Vs reads
        // Load 128 K rows + 128 V rows (2048 float4-tasks each)
#pragma unroll
        for (int p = 0; p < 8; ++p) {
            int idx = tid + 256 * p;
            int r = idx >> 4, q = idx & 15;
            float4 kv = *(const float4*)(Kg + (size_t)(n0 + r) * HSZ + 4 * q);
            *(uint4*)(Ks + r * ASTR + 4 * q) =
                make_uint4(f2tf32(kv.x), f2tf32(kv.y), f2tf32(kv.z), f2tf32(kv.w));
            float4 vv = *(const float4*)(Vg + (size_t)(n0 + r) * HSZ + 4 * q);
            *(uint4*)(Vs + r * ASTR + 4 * q) =
                make_uint4(f2tf32(vv.x), f2tf32(vv.y), f2tf32(vv.z), f2tf32(vv.w));
        }
        __syncthreads();

#pragma unroll
        for (int half = 0; half < 2; ++half) {
            const uint32_t* Kb = Ks + half * 64 * ASTR;
            const uint32_t* Vb = Vs + half * 64 * ASTR;

            // S = Q.K^T  (warp: 16 x 64); Q fragments in registers
            float s[8][4];
#pragma unroll
            for (int nj = 0; nj < 8; ++nj)
#pragma unroll
                for (int q = 0; q < 4; ++q) s[nj][q] = 0.f;
#pragma unroll
            for (int ks = 0; ks < 8; ++ks) {
#pragma unroll
                for (int nj = 0; nj < 8; ++nj) {
                    const uint32_t* pb = Kb + (nj * 8 + g) * ASTR + ks * 8 + t;
                    mma8(s[nj], qfr[ks], pb[0], pb[4]);
                }
            }

            // Online softmax (log2 domain) on fragment rows (g and g+8)
            float mx0 = -1e30f, mx1 = -1e30f;
#pragma unroll
            for (int nj = 0; nj < 8; ++nj) {
                mx0 = fmaxf(mx0, fmaxf(s[nj][0], s[nj][1]));
                mx1 = fmaxf(mx1, fmaxf(s[nj][2], s[nj][3]));
            }
            mx0 = fmaxf(mx0, __shfl_xor_sync(0xffffffffu, mx0, 1));
            mx0 = fmaxf(mx0, __shfl_xor_sync(0xffffffffu, mx0, 2));
            mx1 = fmaxf(mx1, __shfl_xor_sync(0xffffffffu, mx1, 1));
            mx1 = fmaxf(mx1, __shfl_xor_sync(0xffffffffu, mx1, 2));
            float mn0 = fmaxf(m_i[0], mx0), mn1 = fmaxf(m_i[1], mx1);
            float a0 = exp2f(m_i[0] - mn0), a1 = exp2f(m_i[1] - mn1);
            m_i[0] = mn0; m_i[1] = mn1;
            float s0 = 0.f, s1 = 0.f;
#pragma unroll
            for (int nj = 0; nj < 8; ++nj) {
                s[nj][0] = exp2f(s[nj][0] - mn0);
                s[nj][1] = exp2f(s[nj][1] - mn0);
                s[nj][2] = exp2f(s[nj][2] - mn1);
                s[nj][3] = exp2f(s[nj][3] - mn1);
                s0 += s[nj][0] + s[nj][1];
                s1 += s[nj][2] + s[nj][3];
            }
            s0 += __shfl_xor_sync(0xffffffffu, s0, 1);
            s0 += __shfl_xor_sync(0xffffffffu, s0, 2);
            s1 += __shfl_xor_sync(0xffffffffu, s1, 1);
            s1 += __shfl_xor_sync(0xffffffffu, s1, 2);
            l_i[0] = l_i[0] * a0 + s0;
            l_i[1] = l_i[1] * a1 + s1;
#pragma unroll
            for (int nj = 0; nj < 8; ++nj) {
                acc_o[nj][0] *= a0; acc_o[nj][1] *= a0;
                acc_o[nj][2] *= a1; acc_o[nj][3] *= a1;
            }

            // Stage P (per-warp private rows -> warp-level sync only)
            uint32_t* pr0 = Ps + (wrow + g) * ASTR + 2 * t;
            uint32_t* pr1 = Ps + (wrow + g + 8) * ASTR + 2 * t;
#pragma unroll
            for (int nj = 0; nj < 8; ++nj) {
                uint2 w0 = make_uint2(f2tf32(s[nj][0]), f2tf32(s[nj][1]));
                uint2 w1 = make_uint2(f2tf32(s[nj][2]), f2tf32(s[nj][3]));
                *(uint2*)(pr0 + nj * 8) = w0;
                *(uint2*)(pr1 + nj * 8) = w1;
            }
            __syncwarp();

            // O += P.V  (B-frag = transposed read of natural V tile)
#pragma unroll
            for (int ks = 0; ks < 8; ++ks) {
                uint32_t afr[4];
                const uint32_t* pa = Ps + (wrow + g) * ASTR + ks * 8 + t;
                afr[0] = pa[0];
                afr[1] = pa[8 * ASTR];
                afr[2] = pa[4];
                afr[3] = pa[8 * ASTR + 4];
                const uint32_t* vb0 = Vb + (ks * 8 + t) * ASTR + g;
                const uint32_t* vb1 = Vb + (ks * 8 + t + 4) * ASTR + g;
#pragma unroll
                for (int nj = 0; nj < 8; ++nj)
                    mma8(acc_o[nj], afr, vb0[nj * 8], vb1[nj * 8]);
            }
            __syncwarp();   // PV reads of P done before next half overwrites P
        }
    }

    // Epilogue: normalize + write (B,N,C) with head offset
    const int b = bh >> 4, h = bh & 15;
    const float inv0 = 1.f / l_i[0], inv1 = 1.f / l_i[1];
    const int r0 = m0 + wrow + g, r1 = r0 + 8;
#pragma unroll
    for (int nj = 0; nj < 8; ++nj) {
        int col = h * HSZ + nj * 8 + 2 * t;
        *(float2*)(g_attn + ((size_t)(b * SEQ + r0)) * CH + col) =
            make_float2(acc_o[nj][0] * inv0, acc_o[nj][1] * inv0);
        *(float2*)(g_attn + ((size_t)(b * SEQ + r1)) * CH + col) =
            make_float2(acc_o[nj][2] * inv1, acc_o[nj][3] * inv1);
    }
}

// ---------------------------------------------------------------------------
// Output projection (tf32 mma.sync): out[128x128] = g_attn . w_out^T + bias
// (round-4 verified version)
// ---------------------------------------------------------------------------
#define PROJ_SMEM (4*128*SK * 4)   // 73728 B
__global__ __launch_bounds__(256, 2) void proj_tc(const float* __restrict__ W,
                                                  const float* __restrict__ bias,
                                                  float* __restrict__ out) {
    extern __shared__ __align__(16) float sm[];
    uint32_t* sAu = (uint32_t*)sm;
    uint32_t* sBu = (uint32_t*)sm + 2 * 128 * SK;

    const int tid = threadIdx.x, warp = tid >> 5, lane = tid & 31;
    const int wm = warp >> 1, wn = warp & 1;
    const int g = lane >> 2, t = lane & 3;
    const int m0 = blockIdx.y * 128;
    const int n0 = blockIdx.x * 128;

    float acc[2][8][4];
#pragma unroll
    for (int i = 0; i < 2; ++i)
#pragma unroll
        for (int j = 0; j < 8; ++j)
#pragma unroll
            for (int q = 0; q < 4; ++q) acc[i][j][q] = 0.f;

    float4 ar[4], br[4];

    auto LDG = [&](int c) {
        const int k0 = 32 * c;
#pragma unroll
        for (int p = 0; p < 4; ++p) {
            int idx = tid + 256 * p, r = idx >> 3, q = idx & 7;
            ar[p] = *(const float4*)(g_attn + (size_t)(m0 + r) * CH + k0 + 4 * q);
            br[p] = *(const float4*)(W + (size_t)(n0 + r) * CH + k0 + 4 * q);
        }
    };
    auto STS = [&](int buf) {
#pragma unroll
        for (int p = 0; p < 4; ++p) {
            int idx = tid + 256 * p, r = idx >> 3, q = idx & 7;
            uint32_t* dA = sAu + buf * 128 * SK + r * SK + 4 * q;
            dA[0] = f2tf32(ar[p].x); dA[1] = f2tf32(ar[p].y);
            dA[2] = f2tf32(ar[p].z); dA[3] = f2tf32(ar[p].w);
            uint32_t* dB = sBu + buf * 128 * SK + r * SK + 4 * q;
            dB[0] = f2tf32(br[p].x); dB[1] = f2tf32(br[p].y);
            dB[2] = f2tf32(br[p].z); dB[3] = f2tf32(br[p].w);
        }
    };

    LDG(0); STS(0); __syncthreads();

    for (int c = 0; c < 32; ++c) {
        const int buf = c & 1;
        if (c < 31) LDG(c + 1);
        const uint32_t* bA = sAu + buf * 128 * SK;
        const uint32_t* bB = sBu + buf * 128 * SK;
#pragma unroll
        for (int s = 0; s < 4; ++s) {
            uint32_t afr[2][4];
#pragma unroll
            for (int mi = 0; mi < 2; ++mi) {
                const uint32_t* pa = bA + (wm * 32 + mi * 16 + g) * SK + s * 8 + t;
                afr[mi][0] = pa[0];
                afr[mi][1] = pa[8 * SK];
                afr[mi][2] = pa[4];
                afr[mi][3] = pa[8 * SK + 4];
            }
#pragma unroll
            for (int nj = 0; nj < 8; ++nj) {
                const uint32_t* pb = bB + (wn * 64 + nj * 8 + g) * SK + s * 8 + t;
                uint32_t b0 = pb[0], b1 = pb[4];
                mma8(acc[0][nj], afr[0], b0, b1);
                mma8(acc[1][nj], afr[1], b0, b1);
            }
        }
        if (c < 31) STS(buf ^ 1);
        __syncthreads();
    }

#pragma unroll
    for (int mi = 0; mi < 2; ++mi)
#pragma unroll
        for (int nj = 0; nj < 8; ++nj) {
            int row = m0 + wm * 32 + mi * 16 + g;
            int col = n0 + wn * 64 + nj * 8 + 2 * t;
            float b0 = __ldg(bias + col), b1 = __ldg(bias + col + 1);
            *(float2*)(out + (size_t)row * CH + col) =
                make_float2(acc[mi][nj][0] + b0, acc[mi][nj][1] + b1);
            *(float2*)(out + (size_t)(row + 8) * CH + col) =
                make_float2(acc[mi][nj][2] + b0, acc[mi][nj][3] + b1);
        }
}

extern "C" void kernel_launch(void* const* d_in, const int* in_sizes, int n_in,
                              void* d_out, int out_size) {
    const float* x     = (const float*)d_in[0];
    const float* w_qkv = (const float*)d_in[1];
    const float* w_out = (const float*)d_in[2];
    const float* b_out = (const float*)d_in[3];
    float* out = (float*)d_out;

    cudaFuncSetAttribute(qkv_tc, cudaFuncAttributeMaxDynamicSharedMemorySize, QKV_SMEM);
    cudaFuncSetAttribute(attn_tc, cudaFuncAttributeMaxDynamicSharedMemorySize, ATTN_SMEM);
    cudaFuncSetAttribute(proj_tc, cudaFuncAttributeMaxDynamicSharedMemorySize, PROJ_SMEM);

    qkv_tc<<<dim3(32, 32), 256, QKV_SMEM>>>(x, w_qkv);
    attn_tc<<<dim3(SEQ / 128, BATCH * NH), 256, ATTN_SMEM>>>();
    proj_tc<<<dim3(CH / 128, MTOT / 128), 256, PROJ_SMEM>>>(w_out, b_out, out);
}

// round 12
// speedup vs baseline: 1.2800x; 1.0209x over previous
#include <cuda_runtime.h>
#include <cstdint>

#define BATCH 2
#define SEQ   2048
#define CH    1024
#define NH    16
#define HSZ   64
#define MTOT  (BATCH*SEQ)     // 4096
#define QSCALE 0.18033688011112042f   // 0.125 * log2(e): softmax in log2 domain
#define SK    36              // smem row stride (floats) -> conflict-free frags

// Scratch: device globals (no cudaMalloc allowed)
static __device__ float g_q[(size_t)BATCH*NH*SEQ*HSZ];
static __device__ float g_k[(size_t)BATCH*NH*SEQ*HSZ];
static __device__ float g_v[(size_t)BATCH*NH*SEQ*HSZ];
static __device__ float g_attn[(size_t)MTOT*CH];

static __device__ __forceinline__ uint32_t f2tf32(float v) {
    uint32_t r;
    asm("cvt.rna.tf32.f32 %0, %1;" : "=r"(r) : "f"(v));
    return r;
}

static __device__ __forceinline__ uint32_t smem_u32(const void* p) {
    uint32_t a;
    asm("{ .reg .u64 t; cvta.to.shared.u64 t, %1; cvt.u32.u64 %0, t; }" : "=r"(a) : "l"(p));
    return a;
}

static __device__ __forceinline__ void mma8(float* c, const uint32_t* a,
                                            uint32_t b0, uint32_t b1) {
    asm volatile(
        "mma.sync.aligned.m16n8k8.row.col.f32.tf32.tf32.f32 "
        "{%0,%1,%2,%3},{%4,%5,%6,%7},{%8,%9},{%0,%1,%2,%3};"
        : "+f"(c[0]), "+f"(c[1]), "+f"(c[2]), "+f"(c[3])
        : "r"(a[0]), "r"(a[1]), "r"(a[2]), "r"(a[3]), "r"(b0), "r"(b1));
}

// ---------------------------------------------------------------------------
// QKV GEMM (tf32 mma.sync): D[128x96] = x[128,1024] . w_qkv^T slice
// Epilogue stores q/k/v PRE-ROUNDED to tf32 (low 13 mantissa bits zero) so
// attention can cp.async them without a convert pass.
// ---------------------------------------------------------------------------
#define QKV_SMEM ((2*128*SK + 2*96*SK) * 4)   // 64512 B
__global__ __launch_bounds__(256, 2) void qkv_tc(const float* __restrict__ A,
                                                 const float* __restrict__ W) {
    extern __shared__ __align__(16) float sm[];
    uint32_t* sAu = (uint32_t*)sm;
    uint32_t* sBu = (uint32_t*)sm + 2 * 128 * SK;

    const int tid = threadIdx.x, warp = tid >> 5, lane = tid & 31;
    const int wm = warp >> 1, wn = warp & 1;
    const int g = lane >> 2, t = lane & 3;
    const int m0 = blockIdx.y * 128;
    const int bx = blockIdx.x;
    const int n0 = bx * 96;

    float acc[2][6][4];
#pragma unroll
    for (int i = 0; i < 2; ++i)
#pragma unroll
        for (int j = 0; j < 6; ++j)
#pragma unroll
            for (int q = 0; q < 4; ++q) acc[i][j][q] = 0.f;

    float4 ar[4], br[3];

    auto LDG = [&](int c) {
        const int k0 = 32 * c;
#pragma unroll
        for (int p = 0; p < 4; ++p) {
            int idx = tid + 256 * p, r = idx >> 3, q = idx & 7;
            ar[p] = *(const float4*)(A + (size_t)(m0 + r) * CH + k0 + 4 * q);
        }
#pragma unroll
        for (int p = 0; p < 3; ++p) {
            int idx = tid + 256 * p, r = idx >> 3, q = idx & 7;
            br[p] = *(const float4*)(W + (size_t)(n0 + r) * CH + k0 + 4 * q);
        }
    };
    auto STS = [&](int buf) {
#pragma unroll
        for (int p = 0; p < 4; ++p) {
            int idx = tid + 256 * p, r = idx >> 3, q = idx & 7;
            uint32_t* d = sAu + buf * 128 * SK + r * SK + 4 * q;
            d[0] = f2tf32(ar[p].x); d[1] = f2tf32(ar[p].y);
            d[2] = f2tf32(ar[p].z); d[3] = f2tf32(ar[p].w);
        }
#pragma unroll
        for (int p = 0; p < 3; ++p) {
            int idx = tid + 256 * p, r = idx >> 3, q = idx & 7;
            uint32_t* d = sBu + buf * 96 * SK + r * SK + 4 * q;
            d[0] = f2tf32(br[p].x); d[1] = f2tf32(br[p].y);
            d[2] = f2tf32(br[p].z); d[3] = f2tf32(br[p].w);
        }
    };

    LDG(0); STS(0); __syncthreads();

    for (int c = 0; c < 32; ++c) {
        const int buf = c & 1;
        if (c < 31) LDG(c + 1);
        const uint32_t* bA = sAu + buf * 128 * SK;
        const uint32_t* bB = sBu + buf * 96 * SK;
#pragma unroll
        for (int s = 0; s < 4; ++s) {
            uint32_t afr[2][4];
#pragma unroll
            for (int mi = 0; mi < 2; ++mi) {
                const uint32_t* pa = bA + (wm * 32 + mi * 16 + g) * SK + s * 8 + t;
                afr[mi][0] = pa[0];
                afr[mi][1] = pa[8 * SK];
                afr[mi][2] = pa[4];
                afr[mi][3] = pa[8 * SK + 4];
            }
#pragma unroll
            for (int nj = 0; nj < 6; ++nj) {
                const uint32_t* pb = bB + (wn * 48 + nj * 8 + g) * SK + s * 8 + t;
                uint32_t b0 = pb[0], b1 = pb[4];
                mma8(acc[0][nj], afr[0], b0, b1);
                mma8(acc[1][nj], afr[1], b0, b1);
            }
        }
        if (c < 31) STS(buf ^ 1);
        __syncthreads();
    }

    float* Ds = sm;
#pragma unroll
    for (int mi = 0; mi < 2; ++mi)
#pragma unroll
        for (int nj = 0; nj < 6; ++nj) {
            int row = wm * 32 + mi * 16 + g;
            int col = wn * 48 + nj * 8 + 2 * t;
            *(float2*)(Ds + row * 100 + col) =
                make_float2(acc[mi][nj][0], acc[mi][nj][1]);
            *(float2*)(Ds + (row + 8) * 100 + col) =
                make_float2(acc[mi][nj][2], acc[mi][nj][3]);
        }
    __syncthreads();

    const int h = bx >> 1, hs0 = (bx & 1) * 32;
#pragma unroll
    for (int p = 0; p < 12; ++p) {
        int id = tid + 256 * p;
        int c4 = id & 7;
        int s = (id >> 3) % 3;
        int row = id / 24;
        int m = m0 + row;
        int bb = m >> 11, nn = m & 2047;
        float* dst = (s == 0) ? g_q : (s == 1) ? g_k : g_v;
        const float* Dr = Ds + row * 100 + 12 * c4 + s;
        float4 o;
        o.x = __uint_as_float(f2tf32(Dr[0]));
        o.y = __uint_as_float(f2tf32(Dr[3]));
        o.z = __uint_as_float(f2tf32(Dr[6]));
        o.w = __uint_as_float(f2tf32(Dr[9]));
        *(float4*)(dst + ((size_t)(bb * NH + h) * SEQ + nn) * HSZ + hs0 + 4 * c4) = o;
    }
}

// ---------------------------------------------------------------------------
// Flash attention (tf32 mma.sync): CTA = 128 query rows x one (b,h).
// Q fragments in registers. K/V pre-rounded to tf32 -> cp.async straight to
// smem, double-buffered 64-key tiles (loads of tile i+1 overlap compute of i).
// log2-domain softmax. P plain stride-68 (warp-private rows).
// ---------------------------------------------------------------------------
#define ASTR 68
#define ATTN_SMEM (384 * ASTR * 4)   // 104448 B (K 2x64 + V 2x64 + P 128 rows)
__global__ __launch_bounds__(256, 2) void attn_tc() {
    extern __shared__ __align__(16) float sm[];
    uint32_t* Ks = (uint32_t*)sm;               // [2][64][ASTR]
    uint32_t* Vs = Ks + 128 * ASTR;             // [2][64][ASTR]
    uint32_t* Ps = Vs + 128 * ASTR;             // [128][ASTR]
    const uint32_t sbase = smem_u32(sm);

    const int tid = threadIdx.x, warp = tid >> 5, lane = tid & 31;
    const int g = lane >> 2, t = lane & 3;
    const int bh = blockIdx.y;
    const int m0 = blockIdx.x * 128;
    const int wrow = warp * 16;
    const float* Qg = g_q + (size_t)bh * SEQ * HSZ;
    const float* Kg = g_k + (size_t)bh * SEQ * HSZ;
    const float* Vg = g_v + (size_t)bh * SEQ * HSZ;

    // Issue cp.async for one 64-key K/V tile into buffer b (8 x 16B per thread)
    auto CPKV = [&](int n0, int b) {
#pragma unroll
        for (int p = 0; p < 4; ++p) {
            int idx = tid + 256 * p;
            int r = idx >> 4, q = idx & 15;
            const float* gk = Kg + (size_t)(n0 + r) * HSZ + 4 * q;
            uint32_t dk = sbase + (uint32_t)(((b * 64 + r) * ASTR + 4 * q) * 4);
            asm volatile("cp.async.cg.shared.global [%0], [%1], 16;"
                         :: "r"(dk), "l"(gk));
            const float* gv = Vg + (size_t)(n0 + r) * HSZ + 4 * q;
            uint32_t dv = sbase + (uint32_t)(((128 + b * 64 + r) * ASTR + 4 * q) * 4);
            asm volatile("cp.async.cg.shared.global [%0], [%1], 16;"
                         :: "r"(dv), "l"(gv));
        }
        asm volatile("cp.async.commit_group;" ::: "memory");
    };

    // Hoist Q A-fragments into registers (log2e * 0.125 folded in)
    uint32_t qfr[8][4];
    {
        const float* q0 = Qg + (size_t)(m0 + wrow + g) * HSZ;
        const float* q1 = Qg + (size_t)(m0 + wrow + g + 8) * HSZ;
#pragma unroll
        for (int ks = 0; ks < 8; ++ks) {
            int c0 = ks * 8 + t, c1 = c0 + 4;
            qfr[ks][0] = f2tf32(q0[c0] * QSCALE);
            qfr[ks][1] = f2tf32(q1[c0] * QSCALE);
            qfr[ks][2] = f2tf32(q0[c1] * QSCALE);
            qfr[ks][3] = f2tf32(q1[c1] * QSCALE);
        }
    }

    CPKV(0, 0);   // prologue: tile 0 -> buffer 0

    float m_i[2] = {-1e30f, -1e30f};
    float l_i[2] = {0.f, 0.f};
    float acc_o[8][4];
#pragma unroll
    for (int nj = 0; nj < 8; ++nj)
#pragma unroll
        for (int q = 0; q < 4; ++q) acc_o[nj][q] = 0.f;

    for (int kt = 0; kt < 32; ++kt) {
        const int b = kt & 1;
        asm volatile("cp.async.wait_group 0;" ::: "memory");
        __syncthreads();   // tile kt landed everywhere; buf b^1 readers (kt-1) done
        if (kt < 31) CPKV(64 * (kt + 1), b ^ 1);   // overlaps all of tile kt compute

        const uint32_t* Kb = Ks + b * 64 * ASTR;
        const uint32_t* Vb = Vs + b * 64 * ASTR;

        // S = Q.K^T  (warp: 16 x 64); Q fragments in registers
        float s[8][4];
#pragma unroll
        for (int nj = 0; nj < 8; ++nj)
#pragma unroll
            for (int q = 0; q < 4; ++q) s[nj][q] = 0.f;
#pragma unroll
        for (int ks = 0; ks < 8; ++ks) {
#pragma unroll
            for (int nj = 0; nj < 8; ++nj) {
                const uint32_t* pb = Kb + (nj * 8 + g) * ASTR + ks * 8 + t;
                mma8(s[nj], qfr[ks], pb[0], pb[4]);
            }
        }

        // Online softmax (log2 domain) on fragment rows (g and g+8)
        float mx0 = -1e30f, mx1 = -1e30f;
#pragma unroll
        for (int nj = 0; nj < 8; ++nj) {
            mx0 = fmaxf(mx0, fmaxf(s[nj][0], s[nj][1]));
            mx1 = fmaxf(mx1, fmaxf(s[nj][2], s[nj][3]));
        }
        mx0 = fmaxf(mx0, __shfl_xor_sync(0xffffffffu, mx0, 1));
        mx0 = fmaxf(mx0, __shfl_xor_sync(0xffffffffu, mx0, 2));
        mx1 = fmaxf(mx1, __shfl_xor_sync(0xffffffffu, mx1, 1));
        mx1 = fmaxf(mx1, __shfl_xor_sync(0xffffffffu, mx1, 2));
        float mn0 = fmaxf(m_i[0], mx0), mn1 = fmaxf(m_i[1], mx1);
        float a0 = exp2f(m_i[0] - mn0), a1 = exp2f(m_i[1] - mn1);
        m_i[0] = mn0; m_i[1] = mn1;
        float s0 = 0.f, s1 = 0.f;
#pragma unroll
        for (int nj = 0; nj < 8; ++nj) {
            s[nj][0] = exp2f(s[nj][0] - mn0);
            s[nj][1] = exp2f(s[nj][1] - mn0);
            s[nj][2] = exp2f(s[nj][2] - mn1);
            s[nj][3] = exp2f(s[nj][3] - mn1);
            s0 += s[nj][0] + s[nj][1];
            s1 += s[nj][2] + s[nj][3];
        }
        s0 += __shfl_xor_sync(0xffffffffu, s0, 1);
        s0 += __shfl_xor_sync(0xffffffffu, s0, 2);
        s1 += __shfl_xor_sync(0xffffffffu, s1, 1);
        s1 += __shfl_xor_sync(0xffffffffu, s1, 2);
        l_i[0] = l_i[0] * a0 + s0;
        l_i[1] = l_i[1] * a1 + s1;
#pragma unroll
        for (int nj = 0; nj < 8; ++nj) {
            acc_o[nj][0] *= a0; acc_o[nj][1] *= a0;
            acc_o[nj][2] *= a1; acc_o[nj][3] *= a1;
        }

        // Stage P (per-warp private rows -> warp-level sync only)
        uint32_t* pr0 = Ps + (wrow + g) * ASTR + 2 * t;
        uint32_t* pr1 = Ps + (wrow + g + 8) * ASTR + 2 * t;
#pragma unroll
        for (int nj = 0; nj < 8; ++nj) {
            uint2 w0 = make_uint2(f2tf32(s[nj][0]), f2tf32(s[nj][1]));
            uint2 w1 = make_uint2(f2tf32(s[nj][2]), f2tf32(s[nj][3]));
            *(uint2*)(pr0 + nj * 8) = w0;
            *(uint2*)(pr1 + nj * 8) = w1;
        }
        __syncwarp();

        // O += P.V  (B-frag = transposed read of natural V tile)
#pragma unroll
        for (int ks = 0; ks < 8; ++ks) {
            uint32_t afr[4];
            const uint32_t* pa = Ps + (wrow + g) * ASTR + ks * 8 + t;
            afr[0] = pa[0];
            afr[1] = pa[8 * ASTR];
            afr[2] = pa[4];
            afr[3] = pa[8 * ASTR + 4];
            const uint32_t* vb0 = Vb + (ks * 8 + t) * ASTR + g;
            const uint32_t* vb1 = Vb + (ks * 8 + t + 4) * ASTR + g;
#pragma unroll
            for (int nj = 0; nj < 8; ++nj)
                mma8(acc_o[nj], afr, vb0[nj * 8], vb1[nj * 8]);
        }
        __syncwarp();   // this warp's P reads done before next tile overwrites P
    }

    // Epilogue: normalize + write (B,N,C) with head offset
    const int b = bh >> 4, h = bh & 15;
    const float inv0 = 1.f / l_i[0], inv1 = 1.f / l_i[1];
    const int r0 = m0 + wrow + g, r1 = r0 + 8;
#pragma unroll
    for (int nj = 0; nj < 8; ++nj) {
        int col = h * HSZ + nj * 8 + 2 * t;
        *(float2*)(g_attn + ((size_t)(b * SEQ + r0)) * CH + col) =
            make_float2(acc_o[nj][0] * inv0, acc_o[nj][1] * inv0);
        *(float2*)(g_attn + ((size_t)(b * SEQ + r1)) * CH + col) =
            make_float2(acc_o[nj][2] * inv1, acc_o[nj][3] * inv1);
    }
}

// ---------------------------------------------------------------------------
// Output projection (tf32 mma.sync): out[128x128] = g_attn . w_out^T + bias
// (round-4 verified version)
// ---------------------------------------------------------------------------
#define PROJ_SMEM (4*128*SK * 4)   // 73728 B
__global__ __launch_bounds__(256, 2) void proj_tc(const float* __restrict__ W,
                                                  const float* __restrict__ bias,
                                                  float* __restrict__ out) {
    extern __shared__ __align__(16) float sm[];
    uint32_t* sAu = (uint32_t*)sm;
    uint32_t* sBu = (uint32_t*)sm + 2 * 128 * SK;

    const int tid = threadIdx.x, warp = tid >> 5, lane = tid & 31;
    const int wm = warp >> 1, wn = warp & 1;
    const int g = lane >> 2, t = lane & 3;
    const int m0 = blockIdx.y * 128;
    const int n0 = blockIdx.x * 128;

    float acc[2][8][4];
#pragma unroll
    for (int i = 0; i < 2; ++i)
#pragma unroll
        for (int j = 0; j < 8; ++j)
#pragma unroll
            for (int q = 0; q < 4; ++q) acc[i][j][q] = 0.f;

    float4 ar[4], br[4];

    auto LDG = [&](int c) {
        const int k0 = 32 * c;
#pragma unroll
        for (int p = 0; p < 4; ++p) {
            int idx = tid + 256 * p, r = idx >> 3, q = idx & 7;
            ar[p] = *(const float4*)(g_attn + (size_t)(m0 + r) * CH + k0 + 4 * q);
            br[p] = *(const float4*)(W + (size_t)(n0 + r) * CH + k0 + 4 * q);
        }
    };
    auto STS = [&](int buf) {
#pragma unroll
        for (int p = 0; p < 4; ++p) {
            int idx = tid + 256 * p, r = idx >> 3, q = idx & 7;
            uint32_t* dA = sAu + buf * 128 * SK + r * SK + 4 * q;
            dA[0] = f2tf32(ar[p].x); dA[1] = f2tf32(ar[p].y);
            dA[2] = f2tf32(ar[p].z); dA[3] = f2tf32(ar[p].w);
            uint32_t* dB = sBu + buf * 128 * SK + r * SK + 4 * q;
            dB[0] = f2tf32(br[p].x); dB[1] = f2tf32(br[p].y);
            dB[2] = f2tf32(br[p].z); dB[3] = f2tf32(br[p].w);
        }
    };

    LDG(0); STS(0); __syncthreads();

    for (int c = 0; c < 32; ++c) {
        const int buf = c & 1;
        if (c < 31) LDG(c + 1);
        const uint32_t* bA = sAu + buf * 128 * SK;
        const uint32_t* bB = sBu + buf * 128 * SK;
#pragma unroll
        for (int s = 0; s < 4; ++s) {
            uint32_t afr[2][4];
#pragma unroll
            for (int mi = 0; mi < 2; ++mi) {
                const uint32_t* pa = bA + (wm * 32 + mi * 16 + g) * SK + s * 8 + t;
                afr[mi][0] = pa[0];
                afr[mi][1] = pa[8 * SK];
                afr[mi][2] = pa[4];
                afr[mi][3] = pa[8 * SK + 4];
            }
#pragma unroll
            for (int nj = 0; nj < 8; ++nj) {
                const uint32_t* pb = bB + (wn * 64 + nj * 8 + g) * SK + s * 8 + t;
                uint32_t b0 = pb[0], b1 = pb[4];
                mma8(acc[0][nj], afr[0], b0, b1);
                mma8(acc[1][nj], afr[1], b0, b1);
            }
        }
        if (c < 31) STS(buf ^ 1);
        __syncthreads();
    }

#pragma unroll
    for (int mi = 0; mi < 2; ++mi)
#pragma unroll
        for (int nj = 0; nj < 8; ++nj) {
            int row = m0 + wm * 32 + mi * 16 + g;
            int col = n0 + wn * 64 + nj * 8 + 2 * t;
            float b0 = __ldg(bias + col), b1 = __ldg(bias + col + 1);
            *(float2*)(out + (size_t)row * CH + col) =
                make_float2(acc[mi][nj][0] + b0, acc[mi][nj][1] + b1);
            *(float2*)(out + (size_t)(row + 8) * CH + col) =
                make_float2(acc[mi][nj][2] + b0, acc[mi][nj][3] + b1);
        }
}

extern "C" void kernel_launch(void* const* d_in, const int* in_sizes, int n_in,
                              void* d_out, int out_size) {
    const float* x     = (const float*)d_in[0];
    const float* w_qkv = (const float*)d_in[1];
    const float* w_out = (const float*)d_in[2];
    const float* b_out = (const float*)d_in[3];
    float* out = (float*)d_out;

    cudaFuncSetAttribute(qkv_tc, cudaFuncAttributeMaxDynamicSharedMemorySize, QKV_SMEM);
    cudaFuncSetAttribute(attn_tc, cudaFuncAttributeMaxDynamicSharedMemorySize, ATTN_SMEM);
    cudaFuncSetAttribute(proj_tc, cudaFuncAttributeMaxDynamicSharedMemorySize, PROJ_SMEM);

    qkv_tc<<<dim3(32, 32), 256, QKV_SMEM>>>(x, w_qkv);
    attn_tc<<<dim3(SEQ / 128, BATCH * NH), 256, ATTN_SMEM>>>();
    proj_tc<<<dim3(CH / 128, MTOT / 128), 256, PROJ_SMEM>>>(w_out, b_out, out);
}

// round 13
// speedup vs baseline: 1.2831x; 1.0024x over previous
#include <cuda_runtime.h>
#include <cstdint>

#define BATCH 2
#define SEQ   2048
#define CH    1024
#define NH    16
#define HSZ   64
#define MTOT  (BATCH*SEQ)     // 4096
#define QSCALE 0.18033688011112042f   // 0.125 * log2(e): softmax in log2 domain
#define SK    36              // smem row stride (floats) -> conflict-free frags

// Scratch: device globals (no cudaMalloc allowed)
static __device__ float g_q[(size_t)BATCH*NH*SEQ*HSZ];
static __device__ float g_k[(size_t)BATCH*NH*SEQ*HSZ];
static __device__ float g_v[(size_t)BATCH*NH*SEQ*HSZ];
static __device__ float g_attn[(size_t)MTOT*CH];
static __device__ float g_xr[(size_t)MTOT*CH];        // tf32-rounded x
static __device__ float g_wqkvr[(size_t)3*CH*CH];     // tf32-rounded w_qkv
static __device__ float g_woutr[(size_t)CH*CH];       // tf32-rounded w_out

static __device__ __forceinline__ uint32_t f2tf32(float v) {
    uint32_t r;
    asm("cvt.rna.tf32.f32 %0, %1;" : "=r"(r) : "f"(v));
    return r;
}

static __device__ __forceinline__ uint32_t smem_u32(const void* p) {
    uint32_t a;
    asm("{ .reg .u64 t; cvta.to.shared.u64 t, %1; cvt.u32.u64 %0, t; }" : "=r"(a) : "l"(p));
    return a;
}

static __device__ __forceinline__ void cpa16(uint32_t dst, const float* src) {
    asm volatile("cp.async.cg.shared.global [%0], [%1], 16;" :: "r"(dst), "l"(src));
}
#define CP_COMMIT() asm volatile("cp.async.commit_group;" ::: "memory")
#define CP_WAIT0()  asm volatile("cp.async.wait_group 0;" ::: "memory")

static __device__ __forceinline__ void mma8(float* c, const uint32_t* a,
                                            uint32_t b0, uint32_t b1) {
    asm volatile(
        "mma.sync.aligned.m16n8k8.row.col.f32.tf32.tf32.f32 "
        "{%0,%1,%2,%3},{%4,%5,%6,%7},{%8,%9},{%0,%1,%2,%3};"
        : "+f"(c[0]), "+f"(c[1]), "+f"(c[2]), "+f"(c[3])
        : "r"(a[0]), "r"(a[1]), "r"(a[2]), "r"(a[3]), "r"(b0), "r"(b1));
}

// ---------------------------------------------------------------------------
// Pre-pass: round fp32 -> tf32 bit pattern (rna), elementwise.
// ---------------------------------------------------------------------------
__global__ void round_tf32(const float* __restrict__ src, float* __restrict__ dst,
                           int n4) {
    int i = blockIdx.x * blockDim.x + threadIdx.x;
    int stride = gridDim.x * blockDim.x;
    for (; i < n4; i += stride) {
        float4 v = ((const float4*)src)[i];
        uint4 o = make_uint4(f2tf32(v.x), f2tf32(v.y), f2tf32(v.z), f2tf32(v.w));
        ((uint4*)dst)[i] = o;
    }
}

// ---------------------------------------------------------------------------
// QKV GEMM (tf32 mma.sync): D[128x96] = xr[128,1024] . w_qkvr^T slice
// Inputs pre-rounded -> cp.async double-buffered, no cvt/STS in mainloop.
// ---------------------------------------------------------------------------
#define QKV_SMEM ((2*128*SK + 2*96*SK) * 4)   // 64512 B
__global__ __launch_bounds__(256, 2) void qkv_tc(const float* __restrict__ A,
                                                 const float* __restrict__ W) {
    extern __shared__ __align__(16) float sm[];
    const uint32_t sbase = smem_u32(sm);
    const uint32_t aoff[2] = {sbase, sbase + 128u * SK * 4};
    const uint32_t boff[2] = {sbase + 2u * 128 * SK * 4,
                              sbase + 2u * 128 * SK * 4 + 96u * SK * 4};
    uint32_t* sAu = (uint32_t*)sm;
    uint32_t* sBu = (uint32_t*)sm + 2 * 128 * SK;

    const int tid = threadIdx.x, warp = tid >> 5, lane = tid & 31;
    const int wm = warp >> 1, wn = warp & 1;
    const int g = lane >> 2, t = lane & 3;
    const int m0 = blockIdx.y * 128;
    const int bx = blockIdx.x;
    const int n0 = bx * 96;

    float acc[2][6][4];
#pragma unroll
    for (int i = 0; i < 2; ++i)
#pragma unroll
        for (int j = 0; j < 6; ++j)
#pragma unroll
            for (int q = 0; q < 4; ++q) acc[i][j][q] = 0.f;

    auto CPAB = [&](int c, int buf) {
        const int k0 = 32 * c;
#pragma unroll
        for (int p = 0; p < 4; ++p) {
            int idx = tid + 256 * p, r = idx >> 3, q = idx & 7;
            cpa16(aoff[buf] + (uint32_t)((r * SK + 4 * q) * 4),
                  A + (size_t)(m0 + r) * CH + k0 + 4 * q);
        }
#pragma unroll
        for (int p = 0; p < 3; ++p) {
            int idx = tid + 256 * p, r = idx >> 3, q = idx & 7;
            cpa16(boff[buf] + (uint32_t)((r * SK + 4 * q) * 4),
                  W + (size_t)(n0 + r) * CH + k0 + 4 * q);
        }
        CP_COMMIT();
    };

    CPAB(0, 0);

    for (int c = 0; c < 32; ++c) {
        const int buf = c & 1;
        CP_WAIT0();
        __syncthreads();   // chunk c landed; all warps done reading buf (chunk c-2)
        if (c < 31) CPAB(c + 1, buf ^ 1);

        const uint32_t* bA = sAu + buf * 128 * SK;
        const uint32_t* bB = sBu + buf * 96 * SK;
#pragma unroll
        for (int s = 0; s < 4; ++s) {
            uint32_t afr[2][4];
#pragma unroll
            for (int mi = 0; mi < 2; ++mi) {
                const uint32_t* pa = bA + (wm * 32 + mi * 16 + g) * SK + s * 8 + t;
                afr[mi][0] = pa[0];
                afr[mi][1] = pa[8 * SK];
                afr[mi][2] = pa[4];
                afr[mi][3] = pa[8 * SK + 4];
            }
#pragma unroll
            for (int nj = 0; nj < 6; ++nj) {
                const uint32_t* pb = bB + (wn * 48 + nj * 8 + g) * SK + s * 8 + t;
                uint32_t b0 = pb[0], b1 = pb[4];
                mma8(acc[0][nj], afr[0], b0, b1);
                mma8(acc[1][nj], afr[1], b0, b1);
            }
        }
    }
    __syncthreads();   // all compute done before smem is reused for Ds

    float* Ds = sm;
#pragma unroll
    for (int mi = 0; mi < 2; ++mi)
#pragma unroll
        for (int nj = 0; nj < 6; ++nj) {
            int row = wm * 32 + mi * 16 + g;
            int col = wn * 48 + nj * 8 + 2 * t;
            *(float2*)(Ds + row * 100 + col) =
                make_float2(acc[mi][nj][0], acc[mi][nj][1]);
            *(float2*)(Ds + (row + 8) * 100 + col) =
                make_float2(acc[mi][nj][2], acc[mi][nj][3]);
        }
    __syncthreads();

    const int h = bx >> 1, hs0 = (bx & 1) * 32;
#pragma unroll
    for (int p = 0; p < 12; ++p) {
        int id = tid + 256 * p;
        int c4 = id & 7;
        int s = (id >> 3) % 3;
        int row = id / 24;
        int m = m0 + row;
        int bb = m >> 11, nn = m & 2047;
        float* dst = (s == 0) ? g_q : (s == 1) ? g_k : g_v;
        const float* Dr = Ds + row * 100 + 12 * c4 + s;
        float4 o;
        o.x = __uint_as_float(f2tf32(Dr[0]));
        o.y = __uint_as_float(f2tf32(Dr[3]));
        o.z = __uint_as_float(f2tf32(Dr[6]));
        o.w = __uint_as_float(f2tf32(Dr[9]));
        *(float4*)(dst + ((size_t)(bb * NH + h) * SEQ + nn) * HSZ + hs0 + 4 * c4) = o;
    }
}

// ---------------------------------------------------------------------------
// Flash attention (tf32 mma.sync): CTA = 128 query rows x one (b,h).
// Q fragments in registers. K/V pre-rounded -> cp.async double-buffered.
// log2-domain softmax. P plain stride-68 (warp-private rows).
// Epilogue writes g_attn PRE-ROUNDED to tf32 for proj's cp.async path.
// ---------------------------------------------------------------------------
#define ASTR 68
#define ATTN_SMEM (384 * ASTR * 4)   // 104448 B (K 2x64 + V 2x64 + P 128 rows)
__global__ __launch_bounds__(256, 2) void attn_tc() {
    extern __shared__ __align__(16) float sm[];
    uint32_t* Ks = (uint32_t*)sm;               // [2][64][ASTR]
    uint32_t* Vs = Ks + 128 * ASTR;             // [2][64][ASTR]
    uint32_t* Ps = Vs + 128 * ASTR;             // [128][ASTR]
    const uint32_t sbase = smem_u32(sm);

    const int tid = threadIdx.x, warp = tid >> 5, lane = tid & 31;
    const int g = lane >> 2, t = lane & 3;
    const int bh = blockIdx.y;
    const int m0 = blockIdx.x * 128;
    const int wrow = warp * 16;
    const float* Qg = g_q + (size_t)bh * SEQ * HSZ;
    const float* Kg = g_k + (size_t)bh * SEQ * HSZ;
    const float* Vg = g_v + (size_t)bh * SEQ * HSZ;

    auto CPKV = [&](int n0, int b) {
#pragma unroll
        for (int p = 0; p < 4; ++p) {
            int idx = tid + 256 * p;
            int r = idx >> 4, q = idx & 15;
            cpa16(sbase + (uint32_t)(((b * 64 + r) * ASTR + 4 * q) * 4),
                  Kg + (size_t)(n0 + r) * HSZ + 4 * q);
            cpa16(sbase + (uint32_t)(((128 + b * 64 + r) * ASTR + 4 * q) * 4),
                  Vg + (size_t)(n0 + r) * HSZ + 4 * q);
        }
        CP_COMMIT();
    };

    // Hoist Q A-fragments into registers (log2e * 0.125 folded in)
    uint32_t qfr[8][4];
    {
        const float* q0 = Qg + (size_t)(m0 + wrow + g) * HSZ;
        const float* q1 = Qg + (size_t)(m0 + wrow + g + 8) * HSZ;
#pragma unroll
        for (int ks = 0; ks < 8; ++ks) {
            int c0 = ks * 8 + t, c1 = c0 + 4;
            qfr[ks][0] = f2tf32(q0[c0] * QSCALE);
            qfr[ks][1] = f2tf32(q1[c0] * QSCALE);
            qfr[ks][2] = f2tf32(q0[c1] * QSCALE);
            qfr[ks][3] = f2tf32(q1[c1] * QSCALE);
        }
    }

    CPKV(0, 0);

    float m_i[2] = {-1e30f, -1e30f};
    float l_i[2] = {0.f, 0.f};
    float acc_o[8][4];
#pragma unroll
    for (int nj = 0; nj < 8; ++nj)
#pragma unroll
        for (int q = 0; q < 4; ++q) acc_o[nj][q] = 0.f;

    for (int kt = 0; kt < 32; ++kt) {
        const int b = kt & 1;
        CP_WAIT0();
        __syncthreads();
        if (kt < 31) CPKV(64 * (kt + 1), b ^ 1);

        const uint32_t* Kb = Ks + b * 64 * ASTR;
        const uint32_t* Vb = Vs + b * 64 * ASTR;

        // S = Q.K^T  (warp: 16 x 64)
        float s[8][4];
#pragma unroll
        for (int nj = 0; nj < 8; ++nj)
#pragma unroll
            for (int q = 0; q < 4; ++q) s[nj][q] = 0.f;
#pragma unroll
        for (int ks = 0; ks < 8; ++ks) {
#pragma unroll
            for (int nj = 0; nj < 8; ++nj) {
                const uint32_t* pb = Kb + (nj * 8 + g) * ASTR + ks * 8 + t;
                mma8(s[nj], qfr[ks], pb[0], pb[4]);
            }
        }

        // Online softmax (log2 domain) on fragment rows (g and g+8)
        float mx0 = -1e30f, mx1 = -1e30f;
#pragma unroll
        for (int nj = 0; nj < 8; ++nj) {
            mx0 = fmaxf(mx0, fmaxf(s[nj][0], s[nj][1]));
            mx1 = fmaxf(mx1, fmaxf(s[nj][2], s[nj][3]));
        }
        mx0 = fmaxf(mx0, __shfl_xor_sync(0xffffffffu, mx0, 1));
        mx0 = fmaxf(mx0, __shfl_xor_sync(0xffffffffu, mx0, 2));
        mx1 = fmaxf(mx1, __shfl_xor_sync(0xffffffffu, mx1, 1));
        mx1 = fmaxf(mx1, __shfl_xor_sync(0xffffffffu, mx1, 2));
        float mn0 = fmaxf(m_i[0], mx0), mn1 = fmaxf(m_i[1], mx1);
        float a0 = exp2f(m_i[0] - mn0), a1 = exp2f(m_i[1] - mn1);
        m_i[0] = mn0; m_i[1] = mn1;
        float s0 = 0.f, s1 = 0.f;
#pragma unroll
        for (int nj = 0; nj < 8; ++nj) {
            s[nj][0] = exp2f(s[nj][0] - mn0);
            s[nj][1] = exp2f(s[nj][1] - mn0);
            s[nj][2] = exp2f(s[nj][2] - mn1);
            s[nj][3] = exp2f(s[nj][3] - mn1);
            s0 += s[nj][0] + s[nj][1];
            s1 += s[nj][2] + s[nj][3];
        }
        s0 += __shfl_xor_sync(0xffffffffu, s0, 1);
        s0 += __shfl_xor_sync(0xffffffffu, s0, 2);
        s1 += __shfl_xor_sync(0xffffffffu, s1, 1);
        s1 += __shfl_xor_sync(0xffffffffu, s1, 2);
        l_i[0] = l_i[0] * a0 + s0;
        l_i[1] = l_i[1] * a1 + s1;
#pragma unroll
        for (int nj = 0; nj < 8; ++nj) {
            acc_o[nj][0] *= a0; acc_o[nj][1] *= a0;
            acc_o[nj][2] *= a1; acc_o[nj][3] *= a1;
        }

        // Stage P (per-warp private rows)
        uint32_t* pr0 = Ps + (wrow + g) * ASTR + 2 * t;
        uint32_t* pr1 = Ps + (wrow + g + 8) * ASTR + 2 * t;
#pragma unroll
        for (int nj = 0; nj < 8; ++nj) {
            uint2 w0 = make_uint2(f2tf32(s[nj][0]), f2tf32(s[nj][1]));
            uint2 w1 = make_uint2(f2tf32(s[nj][2]), f2tf32(s[nj][3]));
            *(uint2*)(pr0 + nj * 8) = w0;
            *(uint2*)(pr1 + nj * 8) = w1;
        }
        __syncwarp();

        // O += P.V
#pragma unroll
        for (int ks = 0; ks < 8; ++ks) {
            uint32_t afr[4];
            const uint32_t* pa = Ps + (wrow + g) * ASTR + ks * 8 + t;
            afr[0] = pa[0];
            afr[1] = pa[8 * ASTR];
            afr[2] = pa[4];
            afr[3] = pa[8 * ASTR + 4];
            const uint32_t* vb0 = Vb + (ks * 8 + t) * ASTR + g;
            const uint32_t* vb1 = Vb + (ks * 8 + t + 4) * ASTR + g;
#pragma unroll
            for (int nj = 0; nj < 8; ++nj)
                mma8(acc_o[nj], afr, vb0[nj * 8], vb1[nj * 8]);
        }
        __syncwarp();
    }

    // Epilogue: normalize + write (B,N,C), pre-rounded to tf32 for proj
    const int b = bh >> 4, h = bh & 15;
    const float inv0 = 1.f / l_i[0], inv1 = 1.f / l_i[1];
    const int r0 = m0 + wrow + g, r1 = r0 + 8;
#pragma unroll
    for (int nj = 0; nj < 8; ++nj) {
        int col = h * HSZ + nj * 8 + 2 * t;
        float2 o0 = make_float2(__uint_as_float(f2tf32(acc_o[nj][0] * inv0)),
                                __uint_as_float(f2tf32(acc_o[nj][1] * inv0)));
        float2 o1 = make_float2(__uint_as_float(f2tf32(acc_o[nj][2] * inv1)),
                                __uint_as_float(f2tf32(acc_o[nj][3] * inv1)));
        *(float2*)(g_attn + ((size_t)(b * SEQ + r0)) * CH + col) = o0;
        *(float2*)(g_attn + ((size_t)(b * SEQ + r1)) * CH + col) = o1;
    }
}

// ---------------------------------------------------------------------------
// Output projection (tf32 mma.sync): out[128x128] = g_attn . w_outr^T + bias
// Both inputs pre-rounded -> cp.async double-buffered.
// ---------------------------------------------------------------------------
#define PROJ_SMEM (4*128*SK * 4)   // 73728 B
__global__ __launch_bounds__(256, 2) void proj_tc(const float* __restrict__ W,
                                                  const float* __restrict__ bias,
                                                  float* __restrict__ out) {
    extern __shared__ __align__(16) float sm[];
    const uint32_t sbase = smem_u32(sm);
    uint32_t* sAu = (uint32_t*)sm;
    uint32_t* sBu = (uint32_t*)sm + 2 * 128 * SK;
    const uint32_t aoff[2] = {sbase, sbase + 128u * SK * 4};
    const uint32_t boff[2] = {sbase + 2u * 128 * SK * 4,
                              sbase + 3u * 128 * SK * 4};

    const int tid = threadIdx.x, warp = tid >> 5, lane = tid & 31;
    const int wm = warp >> 1, wn = warp & 1;
    const int g = lane >> 2, t = lane & 3;
    const int m0 = blockIdx.y * 128;
    const int n0 = blockIdx.x * 128;

    float acc[2][8][4];
#pragma unroll
    for (int i = 0; i < 2; ++i)
#pragma unroll
        for (int j = 0; j < 8; ++j)
#pragma unroll
            for (int q = 0; q < 4; ++q) acc[i][j][q] = 0.f;

    auto CPAB = [&](int c, int buf) {
        const int k0 = 32 * c;
#pragma unroll
        for (int p = 0; p < 4; ++p) {
            int idx = tid + 256 * p, r = idx >> 3, q = idx & 7;
            cpa16(aoff[buf] + (uint32_t)((r * SK + 4 * q) * 4),
                  g_attn + (size_t)(m0 + r) * CH + k0 + 4 * q);
            cpa16(boff[buf] + (uint32_t)((r * SK + 4 * q) * 4),
                  W + (size_t)(n0 + r) * CH + k0 + 4 * q);
        }
        CP_COMMIT();
    };

    CPAB(0, 0);

    for (int c = 0; c < 32; ++c) {
        const int buf = c & 1;
        CP_WAIT0();
        __syncthreads();
        if (c < 31) CPAB(c + 1, buf ^ 1);

        const uint32_t* bA = sAu + buf * 128 * SK;
        const uint32_t* bB = sBu + buf * 128 * SK;
#pragma unroll
        for (int s = 0; s < 4; ++s) {
            uint32_t afr[2][4];
#pragma unroll
            for (int mi = 0; mi < 2; ++mi) {
                const uint32_t* pa = bA + (wm * 32 + mi * 16 + g) * SK + s * 8 + t;
                afr[mi][0] = pa[0];
                afr[mi][1] = pa[8 * SK];
                afr[mi][2] = pa[4];
                afr[mi][3] = pa[8 * SK + 4];
            }
#pragma unroll
            for (int nj = 0; nj < 8; ++nj) {
                const uint32_t* pb = bB + (wn * 64 + nj * 8 + g) * SK + s * 8 + t;
                uint32_t b0 = pb[0], b1 = pb[4];
                mma8(acc[0][nj], afr[0], b0, b1);
                mma8(acc[1][nj], afr[1], b0, b1);
            }
        }
    }

#pragma unroll
    for (int mi = 0; mi < 2; ++mi)
#pragma unroll
        for (int nj = 0; nj < 8; ++nj) {
            int row = m0 + wm * 32 + mi * 16 + g;
            int col = n0 + wn * 64 + nj * 8 + 2 * t;
            float b0 = __ldg(bias + col), b1 = __ldg(bias + col + 1);
            *(float2*)(out + (size_t)row * CH + col) =
                make_float2(acc[mi][nj][0] + b0, acc[mi][nj][1] + b1);
            *(float2*)(out + (size_t)(row + 8) * CH + col) =
                make_float2(acc[mi][nj][2] + b0, acc[mi][nj][3] + b1);
        }
}

extern "C" void kernel_launch(void* const* d_in, const int* in_sizes, int n_in,
                              void* d_out, int out_size) {
    const float* x     = (const float*)d_in[0];
    const float* w_qkv = (const float*)d_in[1];
    const float* w_out = (const float*)d_in[2];
    const float* b_out = (const float*)d_in[3];
    float* out = (float*)d_out;

    cudaFuncSetAttribute(qkv_tc, cudaFuncAttributeMaxDynamicSharedMemorySize, QKV_SMEM);
    cudaFuncSetAttribute(attn_tc, cudaFuncAttributeMaxDynamicSharedMemorySize, ATTN_SMEM);
    cudaFuncSetAttribute(proj_tc, cudaFuncAttributeMaxDynamicSharedMemorySize, PROJ_SMEM);

    float* d_xr;    cudaGetSymbolAddress((void**)&d_xr, g_xr);
    float* d_wqkvr; cudaGetSymbolAddress((void**)&d_wqkvr, g_wqkvr);
    float* d_woutr; cudaGetSymbolAddress((void**)&d_woutr, g_woutr);

    round_tf32<<<1184, 256>>>(x, d_xr, MTOT * CH / 4);
    round_tf32<<<1184, 256>>>(w_qkv, d_wqkvr, 3 * CH * CH / 4);
    round_tf32<<<1184, 256>>>(w_out, d_woutr, CH * CH / 4);

    qkv_tc<<<dim3(32, 32), 256, QKV_SMEM>>>(d_xr, d_wqkvr);
    attn_tc<<<dim3(SEQ / 128, BATCH * NH), 256, ATTN_SMEM>>>();
    proj_tc<<<dim3(CH / 128, MTOT / 128), 256, PROJ_SMEM>>>(d_woutr, b_out, out);
}

// round 14
// speedup vs baseline: 1.3012x; 1.0141x over previous
#include <cuda_runtime.h>
#include <cstdint>

#define BATCH 2
#define SEQ   2048
#define CH    1024
#define NH    16
#define HSZ   64
#define MTOT  (BATCH*SEQ)     // 4096
#define QSCALE 0.18033688011112042f   // 0.125 * log2(e): softmax in log2 domain
#define SK    36              // smem row stride (floats) -> conflict-free frags

// Scratch: device globals (no cudaMalloc allowed)
static __device__ float g_q[(size_t)BATCH*NH*SEQ*HSZ];
static __device__ float g_k[(size_t)BATCH*NH*SEQ*HSZ];
static __device__ float g_v[(size_t)BATCH*NH*SEQ*HSZ];
static __device__ float g_attn[(size_t)MTOT*CH];
static __device__ float g_xr[(size_t)MTOT*CH];        // tf32-rounded x
static __device__ float g_wqkvr[(size_t)3*CH*CH];     // tf32-rounded w_qkv
static __device__ float g_woutr[(size_t)CH*CH];       // tf32-rounded w_out

static __device__ __forceinline__ uint32_t f2tf32(float v) {
    uint32_t r;
    asm("cvt.rna.tf32.f32 %0, %1;" : "=r"(r) : "f"(v));
    return r;
}

static __device__ __forceinline__ uint32_t smem_u32(const void* p) {
    uint32_t a;
    asm("{ .reg .u64 t; cvta.to.shared.u64 t, %1; cvt.u32.u64 %0, t; }" : "=r"(a) : "l"(p));
    return a;
}

static __device__ __forceinline__ void cpa16(uint32_t dst, const float* src) {
    asm volatile("cp.async.cg.shared.global [%0], [%1], 16;" :: "r"(dst), "l"(src));
}
#define CP_COMMIT() asm volatile("cp.async.commit_group;" ::: "memory")
#define CP_WAIT0()  asm volatile("cp.async.wait_group 0;" ::: "memory")
#define CP_WAIT1()  asm volatile("cp.async.wait_group 1;" ::: "memory")

static __device__ __forceinline__ void mma8(float* c, const uint32_t* a,
                                            uint32_t b0, uint32_t b1) {
    asm volatile(
        "mma.sync.aligned.m16n8k8.row.col.f32.tf32.tf32.f32 "
        "{%0,%1,%2,%3},{%4,%5,%6,%7},{%8,%9},{%0,%1,%2,%3};"
        : "+f"(c[0]), "+f"(c[1]), "+f"(c[2]), "+f"(c[3])
        : "r"(a[0]), "r"(a[1]), "r"(a[2]), "r"(a[3]), "r"(b0), "r"(b1));
}

// ---------------------------------------------------------------------------
// Fused pre-pass: round x, w_qkv, w_out fp32 -> tf32 (rna) in ONE launch.
// ---------------------------------------------------------------------------
#define N4_X    (MTOT*CH/4)            // 1048576
#define N4_WQKV (3*CH*CH/4)            // 786432
#define N4_WOUT (CH*CH/4)              // 262144
#define N4_ALL  (N4_X + N4_WQKV + N4_WOUT)
__global__ void round_all(const float* __restrict__ x, const float* __restrict__ wq,
                          const float* __restrict__ wo) {
    int i = blockIdx.x * blockDim.x + threadIdx.x;
    int stride = gridDim.x * blockDim.x;
    for (; i < N4_ALL; i += stride) {
        const float* src; float* dst; int j;
        if (i < N4_X)                 { src = x;  dst = g_xr;    j = i; }
        else if (i < N4_X + N4_WQKV)  { src = wq; dst = g_wqkvr; j = i - N4_X; }
        else                          { src = wo; dst = g_woutr; j = i - N4_X - N4_WQKV; }
        float4 v = ((const float4*)src)[j];
        uint4 o = make_uint4(f2tf32(v.x), f2tf32(v.y), f2tf32(v.z), f2tf32(v.w));
        ((uint4*)dst)[j] = o;
    }
}

// ---------------------------------------------------------------------------
// QKV GEMM (tf32 mma.sync): D[128x96] = xr[128,1024] . w_qkvr^T slice
// Pre-rounded inputs, 3-stage cp.async pipeline (wait_group 1 steady state).
// ---------------------------------------------------------------------------
#define QKV_SMEM (3*(128+96)*SK*4)   // 96768 B
__global__ __launch_bounds__(256, 2) void qkv_tc() {
    extern __shared__ __align__(16) float sm[];
    const uint32_t sbase = smem_u32(sm);
    uint32_t* sAu = (uint32_t*)sm;                 // 3 bufs x 128*SK
    uint32_t* sBu = (uint32_t*)sm + 3 * 128 * SK;  // 3 bufs x 96*SK
    const float* A = g_xr;
    const float* W = g_wqkvr;

    const int tid = threadIdx.x, warp = tid >> 5, lane = tid & 31;
    const int wm = warp >> 1, wn = warp & 1;
    const int g = lane >> 2, t = lane & 3;
    const int m0 = blockIdx.y * 128;
    const int bx = blockIdx.x;
    const int n0 = bx * 96;

    float acc[2][6][4];
#pragma unroll
    for (int i = 0; i < 2; ++i)
#pragma unroll
        for (int j = 0; j < 6; ++j)
#pragma unroll
            for (int q = 0; q < 4; ++q) acc[i][j][q] = 0.f;

    auto CPAB = [&](int c, int buf) {
        const int k0 = 32 * c;
        const uint32_t ao = sbase + (uint32_t)(buf * 128 * SK * 4);
        const uint32_t bo = sbase + (uint32_t)((3 * 128 + buf * 96) * SK * 4);
#pragma unroll
        for (int p = 0; p < 4; ++p) {
            int idx = tid + 256 * p, r = idx >> 3, q = idx & 7;
            cpa16(ao + (uint32_t)((r * SK + 4 * q) * 4),
                  A + (size_t)(m0 + r) * CH + k0 + 4 * q);
        }
#pragma unroll
        for (int p = 0; p < 3; ++p) {
            int idx = tid + 256 * p, r = idx >> 3, q = idx & 7;
            cpa16(bo + (uint32_t)((r * SK + 4 * q) * 4),
                  W + (size_t)(n0 + r) * CH + k0 + 4 * q);
        }
        CP_COMMIT();
    };

    CPAB(0, 0);
    CPAB(1, 1);

    for (int c = 0; c < 32; ++c) {
        const int buf = c % 3;
        if (c == 31) CP_WAIT0(); else CP_WAIT1();   // chunk c resident
        __syncthreads();    // all warps past chunk c-1 reads -> buf (c+2)%3 reusable
        if (c < 30) CPAB(c + 2, (c + 2) % 3);

        const uint32_t* bA = sAu + buf * 128 * SK;
        const uint32_t* bB = sBu + buf * 96 * SK;
#pragma unroll
        for (int s = 0; s < 4; ++s) {
            uint32_t afr[2][4];
#pragma unroll
            for (int mi = 0; mi < 2; ++mi) {
                const uint32_t* pa = bA + (wm * 32 + mi * 16 + g) * SK + s * 8 + t;
                afr[mi][0] = pa[0];
                afr[mi][1] = pa[8 * SK];
                afr[mi][2] = pa[4];
                afr[mi][3] = pa[8 * SK + 4];
            }
#pragma unroll
            for (int nj = 0; nj < 6; ++nj) {
                const uint32_t* pb = bB + (wn * 48 + nj * 8 + g) * SK + s * 8 + t;
                uint32_t b0 = pb[0], b1 = pb[4];
                mma8(acc[0][nj], afr[0], b0, b1);
                mma8(acc[1][nj], afr[1], b0, b1);
            }
        }
    }
    __syncthreads();   // all compute done before smem reuse for Ds

    float* Ds = sm;
#pragma unroll
    for (int mi = 0; mi < 2; ++mi)
#pragma unroll
        for (int nj = 0; nj < 6; ++nj) {
            int row = wm * 32 + mi * 16 + g;
            int col = wn * 48 + nj * 8 + 2 * t;
            *(float2*)(Ds + row * 100 + col) =
                make_float2(acc[mi][nj][0], acc[mi][nj][1]);
            *(float2*)(Ds + (row + 8) * 100 + col) =
                make_float2(acc[mi][nj][2], acc[mi][nj][3]);
        }
    __syncthreads();

    const int h = bx >> 1, hs0 = (bx & 1) * 32;
#pragma unroll
    for (int p = 0; p < 12; ++p) {
        int id = tid + 256 * p;
        int c4 = id & 7;
        int s = (id >> 3) % 3;
        int row = id / 24;
        int m = m0 + row;
        int bb = m >> 11, nn = m & 2047;
        float* dst = (s == 0) ? g_q : (s == 1) ? g_k : g_v;
        const float* Dr = Ds + row * 100 + 12 * c4 + s;
        float4 o;
        o.x = __uint_as_float(f2tf32(Dr[0]));
        o.y = __uint_as_float(f2tf32(Dr[3]));
        o.z = __uint_as_float(f2tf32(Dr[6]));
        o.w = __uint_as_float(f2tf32(Dr[9]));
        *(float4*)(dst + ((size_t)(bb * NH + h) * SEQ + nn) * HSZ + hs0 + 4 * c4) = o;
    }
}

// ---------------------------------------------------------------------------
// Flash attention (tf32 mma.sync): unchanged verified round-13 version.
// ---------------------------------------------------------------------------
#define ASTR 68
#define ATTN_SMEM (384 * ASTR * 4)   // 104448 B (K 2x64 + V 2x64 + P 128 rows)
__global__ __launch_bounds__(256, 2) void attn_tc() {
    extern __shared__ __align__(16) float sm[];
    uint32_t* Ks = (uint32_t*)sm;               // [2][64][ASTR]
    uint32_t* Vs = Ks + 128 * ASTR;             // [2][64][ASTR]
    uint32_t* Ps = Vs + 128 * ASTR;             // [128][ASTR]
    const uint32_t sbase = smem_u32(sm);

    const int tid = threadIdx.x, warp = tid >> 5, lane = tid & 31;
    const int g = lane >> 2, t = lane & 3;
    const int bh = blockIdx.y;
    const int m0 = blockIdx.x * 128;
    const int wrow = warp * 16;
    const float* Qg = g_q + (size_t)bh * SEQ * HSZ;
    const float* Kg = g_k + (size_t)bh * SEQ * HSZ;
    const float* Vg = g_v + (size_t)bh * SEQ * HSZ;

    auto CPKV = [&](int n0, int b) {
#pragma unroll
        for (int p = 0; p < 4; ++p) {
            int idx = tid + 256 * p;
            int r = idx >> 4, q = idx & 15;
            cpa16(sbase + (uint32_t)(((b * 64 + r) * ASTR + 4 * q) * 4),
                  Kg + (size_t)(n0 + r) * HSZ + 4 * q);
            cpa16(sbase + (uint32_t)(((128 + b * 64 + r) * ASTR + 4 * q) * 4),
                  Vg + (size_t)(n0 + r) * HSZ + 4 * q);
        }
        CP_COMMIT();
    };

    uint32_t qfr[8][4];
    {
        const float* q0 = Qg + (size_t)(m0 + wrow + g) * HSZ;
        const float* q1 = Qg + (size_t)(m0 + wrow + g + 8) * HSZ;
#pragma unroll
        for (int ks = 0; ks < 8; ++ks) {
            int c0 = ks * 8 + t, c1 = c0 + 4;
            qfr[ks][0] = f2tf32(q0[c0] * QSCALE);
            qfr[ks][1] = f2tf32(q1[c0] * QSCALE);
            qfr[ks][2] = f2tf32(q0[c1] * QSCALE);
            qfr[ks][3] = f2tf32(q1[c1] * QSCALE);
        }
    }

    CPKV(0, 0);

    float m_i[2] = {-1e30f, -1e30f};
    float l_i[2] = {0.f, 0.f};
    float acc_o[8][4];
#pragma unroll
    for (int nj = 0; nj < 8; ++nj)
#pragma unroll
        for (int q = 0; q < 4; ++q) acc_o[nj][q] = 0.f;

    for (int kt = 0; kt < 32; ++kt) {
        const int b = kt & 1;
        CP_WAIT0();
        __syncthreads();
        if (kt < 31) CPKV(64 * (kt + 1), b ^ 1);

        const uint32_t* Kb = Ks + b * 64 * ASTR;
        const uint32_t* Vb = Vs + b * 64 * ASTR;

        float s[8][4];
#pragma unroll
        for (int nj = 0; nj < 8; ++nj)
#pragma unroll
            for (int q = 0; q < 4; ++q) s[nj][q] = 0.f;
#pragma unroll
        for (int ks = 0; ks < 8; ++ks) {
#pragma unroll
            for (int nj = 0; nj < 8; ++nj) {
                const uint32_t* pb = Kb + (nj * 8 + g) * ASTR + ks * 8 + t;
                mma8(s[nj], qfr[ks], pb[0], pb[4]);
            }
        }

        float mx0 = -1e30f, mx1 = -1e30f;
#pragma unroll
        for (int nj = 0; nj < 8; ++nj) {
            mx0 = fmaxf(mx0, fmaxf(s[nj][0], s[nj][1]));
            mx1 = fmaxf(mx1, fmaxf(s[nj][2], s[nj][3]));
        }
        mx0 = fmaxf(mx0, __shfl_xor_sync(0xffffffffu, mx0, 1));
        mx0 = fmaxf(mx0, __shfl_xor_sync(0xffffffffu, mx0, 2));
        mx1 = fmaxf(mx1, __shfl_xor_sync(0xffffffffu, mx1, 1));
        mx1 = fmaxf(mx1, __shfl_xor_sync(0xffffffffu, mx1, 2));
        float mn0 = fmaxf(m_i[0], mx0), mn1 = fmaxf(m_i[1], mx1);
        float a0 = exp2f(m_i[0] - mn0), a1 = exp2f(m_i[1] - mn1);
        m_i[0] = mn0; m_i[1] = mn1;
        float s0 = 0.f, s1 = 0.f;
#pragma unroll
        for (int nj = 0; nj < 8; ++nj) {
            s[nj][0] = exp2f(s[nj][0] - mn0);
            s[nj][1] = exp2f(s[nj][1] - mn0);
            s[nj][2] = exp2f(s[nj][2] - mn1);
            s[nj][3] = exp2f(s[nj][3] - mn1);
            s0 += s[nj][0] + s[nj][1];
            s1 += s[nj][2] + s[nj][3];
        }
        s0 += __shfl_xor_sync(0xffffffffu, s0, 1);
        s0 += __shfl_xor_sync(0xffffffffu, s0, 2);
        s1 += __shfl_xor_sync(0xffffffffu, s1, 1);
        s1 += __shfl_xor_sync(0xffffffffu, s1, 2);
        l_i[0] = l_i[0] * a0 + s0;
        l_i[1] = l_i[1] * a1 + s1;
#pragma unroll
        for (int nj = 0; nj < 8; ++nj) {
            acc_o[nj][0] *= a0; acc_o[nj][1] *= a0;
            acc_o[nj][2] *= a1; acc_o[nj][3] *= a1;
        }

        uint32_t* pr0 = Ps + (wrow + g) * ASTR + 2 * t;
        uint32_t* pr1 = Ps + (wrow + g + 8) * ASTR + 2 * t;
#pragma unroll
        for (int nj = 0; nj < 8; ++nj) {
            uint2 w0 = make_uint2(f2tf32(s[nj][0]), f2tf32(s[nj][1]));
            uint2 w1 = make_uint2(f2tf32(s[nj][2]), f2tf32(s[nj][3]));
            *(uint2*)(pr0 + nj * 8) = w0;
            *(uint2*)(pr1 + nj * 8) = w1;
        }
        __syncwarp();

#pragma unroll
        for (int ks = 0; ks < 8; ++ks) {
            uint32_t afr[4];
            const uint32_t* pa = Ps + (wrow + g) * ASTR + ks * 8 + t;
            afr[0] = pa[0];
            afr[1] = pa[8 * ASTR];
            afr[2] = pa[4];
            afr[3] = pa[8 * ASTR + 4];
            const uint32_t* vb0 = Vb + (ks * 8 + t) * ASTR + g;
            const uint32_t* vb1 = Vb + (ks * 8 + t + 4) * ASTR + g;
#pragma unroll
            for (int nj = 0; nj < 8; ++nj)
                mma8(acc_o[nj], afr, vb0[nj * 8], vb1[nj * 8]);
        }
        __syncwarp();
    }

    const int b = bh >> 4, h = bh & 15;
    const float inv0 = 1.f / l_i[0], inv1 = 1.f / l_i[1];
    const int r0 = m0 + wrow + g, r1 = r0 + 8;
#pragma unroll
    for (int nj = 0; nj < 8; ++nj) {
        int col = h * HSZ + nj * 8 + 2 * t;
        float2 o0 = make_float2(__uint_as_float(f2tf32(acc_o[nj][0] * inv0)),
                                __uint_as_float(f2tf32(acc_o[nj][1] * inv0)));
        float2 o1 = make_float2(__uint_as_float(f2tf32(acc_o[nj][2] * inv1)),
                                __uint_as_float(f2tf32(acc_o[nj][3] * inv1)));
        *(float2*)(g_attn + ((size_t)(b * SEQ + r0)) * CH + col) = o0;
        *(float2*)(g_attn + ((size_t)(b * SEQ + r1)) * CH + col) = o1;
    }
}

// ---------------------------------------------------------------------------
// Output projection (tf32 mma.sync): out[128x128] = g_attn . w_outr^T + bias
// Pre-rounded inputs, 3-stage cp.async pipeline.
// ---------------------------------------------------------------------------
#define PROJ_SMEM (3*2*128*SK*4)   // 110592 B
__global__ __launch_bounds__(256, 2) void proj_tc(const float* __restrict__ bias,
                                                  float* __restrict__ out) {
    extern __shared__ __align__(16) float sm[];
    const uint32_t sbase = smem_u32(sm);
    uint32_t* sAu = (uint32_t*)sm;                 // 3 bufs x 128*SK
    uint32_t* sBu = (uint32_t*)sm + 3 * 128 * SK;  // 3 bufs x 128*SK
    const float* W = g_woutr;

    const int tid = threadIdx.x, warp = tid >> 5, lane = tid & 31;
    const int wm = warp >> 1, wn = warp & 1;
    const int g = lane >> 2, t = lane & 3;
    const int m0 = blockIdx.y * 128;
    const int n0 = blockIdx.x * 128;

    float acc[2][8][4];
#pragma unroll
    for (int i = 0; i < 2; ++i)
#pragma unroll
        for (int j = 0; j < 8; ++j)
#pragma unroll
            for (int q = 0; q < 4; ++q) acc[i][j][q] = 0.f;

    auto CPAB = [&](int c, int buf) {
        const int k0 = 32 * c;
        const uint32_t ao = sbase + (uint32_t)(buf * 128 * SK * 4);
        const uint32_t bo = sbase + (uint32_t)((3 + buf) * 128 * SK * 4);
#pragma unroll
        for (int p = 0; p < 4; ++p) {
            int idx = tid + 256 * p, r = idx >> 3, q = idx & 7;
            cpa16(ao + (uint32_t)((r * SK + 4 * q) * 4),
                  g_attn + (size_t)(m0 + r) * CH + k0 + 4 * q);
            cpa16(bo + (uint32_t)((r * SK + 4 * q) * 4),
                  W + (size_t)(n0 + r) * CH + k0 + 4 * q);
        }
        CP_COMMIT();
    };

    CPAB(0, 0);
    CPAB(1, 1);

    for (int c = 0; c < 32; ++c) {
        const int buf = c % 3;
        if (c == 31) CP_WAIT0(); else CP_WAIT1();
        __syncthreads();
        if (c < 30) CPAB(c + 2, (c + 2) % 3);

        const uint32_t* bA = sAu + buf * 128 * SK;
        const uint32_t* bB = sBu + buf * 128 * SK;
#pragma unroll
        for (int s = 0; s < 4; ++s) {
            uint32_t afr[2][4];
#pragma unroll
            for (int mi = 0; mi < 2; ++mi) {
                const uint32_t* pa = bA + (wm * 32 + mi * 16 + g) * SK + s * 8 + t;
                afr[mi][0] = pa[0];
                afr[mi][1] = pa[8 * SK];
                afr[mi][2] = pa[4];
                afr[mi][3] = pa[8 * SK + 4];
            }
#pragma unroll
            for (int nj = 0; nj < 8; ++nj) {
                const uint32_t* pb = bB + (wn * 64 + nj * 8 + g) * SK + s * 8 + t;
                uint32_t b0 = pb[0], b1 = pb[4];
                mma8(acc[0][nj], afr[0], b0, b1);
                mma8(acc[1][nj], afr[1], b0, b1);
            }
        }
    }

#pragma unroll
    for (int mi = 0; mi < 2; ++mi)
#pragma unroll
        for (int nj = 0; nj < 8; ++nj) {
            int row = m0 + wm * 32 + mi * 16 + g;
            int col = n0 + wn * 64 + nj * 8 + 2 * t;
            float b0 = __ldg(bias + col), b1 = __ldg(bias + col + 1);
            *(float2*)(out + (size_t)row * CH + col) =
                make_float2(acc[mi][nj][0] + b0, acc[mi][nj][1] + b1);
            *(float2*)(out + (size_t)(row + 8) * CH + col) =
                make_float2(acc[mi][nj][2] + b0, acc[mi][nj][3] + b1);
        }
}

extern "C" void kernel_launch(void* const* d_in, const int* in_sizes, int n_in,
                              void* d_out, int out_size) {
    const float* x     = (const float*)d_in[0];
    const float* w_qkv = (const float*)d_in[1];
    const float* w_out = (const float*)d_in[2];
    const float* b_out = (const float*)d_in[3];
    float* out = (float*)d_out;

    cudaFuncSetAttribute(qkv_tc, cudaFuncAttributeMaxDynamicSharedMemorySize, QKV_SMEM);
    cudaFuncSetAttribute(attn_tc, cudaFuncAttributeMaxDynamicSharedMemorySize, ATTN_SMEM);
    cudaFuncSetAttribute(proj_tc, cudaFuncAttributeMaxDynamicSharedMemorySize, PROJ_SMEM);

    round_all<<<2368, 256>>>(x, w_qkv, w_out);
    qkv_tc<<<dim3(32, 32), 256, QKV_SMEM>>>();
    attn_tc<<<dim3(SEQ / 128, BATCH * NH), 256, ATTN_SMEM>>>();
    proj_tc<<<dim3(CH / 128, MTOT / 128), 256, PROJ_SMEM>>>(b_out, out);
}

// round 15
// speedup vs baseline: 1.4680x; 1.1281x over previous
#include <cuda_runtime.h>
#include <cstdint>

#define BATCH 2
#define SEQ   2048
#define CH    1024
#define NH    16
#define HSZ   64
#define MTOT  (BATCH*SEQ)     // 4096
#define QSCALE 0.18033688011112042f   // 0.125 * log2(e): softmax in log2 domain
#define SK    36              // GEMM smem row stride (floats) -> conflict-free frags

// Scratch: device globals (no cudaMalloc allowed)
static __device__ float g_q[(size_t)BATCH*NH*SEQ*HSZ];
static __device__ float g_k[(size_t)BATCH*NH*SEQ*HSZ];
static __device__ float g_v[(size_t)BATCH*NH*SEQ*HSZ];
static __device__ float g_attn[(size_t)MTOT*CH];
static __device__ float g_xr[(size_t)MTOT*CH];        // tf32-rounded x
static __device__ float g_wqkvr[(size_t)3*CH*CH];     // tf32-rounded w_qkv
static __device__ float g_woutr[(size_t)CH*CH];       // tf32-rounded w_out

static __device__ __forceinline__ uint32_t f2tf32(float v) {
    uint32_t r;
    asm("cvt.rna.tf32.f32 %0, %1;" : "=r"(r) : "f"(v));
    return r;
}

static __device__ __forceinline__ float ex2(float x) {
    float r;
    asm("ex2.approx.ftz.f32 %0, %1;" : "=f"(r) : "f"(x));
    return r;
}

static __device__ __forceinline__ uint32_t smem_u32(const void* p) {
    uint32_t a;
    asm("{ .reg .u64 t; cvta.to.shared.u64 t, %1; cvt.u32.u64 %0, t; }" : "=r"(a) : "l"(p));
    return a;
}

static __device__ __forceinline__ void cpa16(uint32_t dst, const float* src) {
    asm volatile("cp.async.cg.shared.global [%0], [%1], 16;" :: "r"(dst), "l"(src));
}
#define CP_COMMIT() asm volatile("cp.async.commit_group;" ::: "memory")
#define CP_WAIT0()  asm volatile("cp.async.wait_group 0;" ::: "memory")
#define CP_WAIT1()  asm volatile("cp.async.wait_group 1;" ::: "memory")

static __device__ __forceinline__ void mma8(float* c, const uint32_t* a,
                                            uint32_t b0, uint32_t b1) {
    asm volatile(
        "mma.sync.aligned.m16n8k8.row.col.f32.tf32.tf32.f32 "
        "{%0,%1,%2,%3},{%4,%5,%6,%7},{%8,%9},{%0,%1,%2,%3};"
        : "+f"(c[0]), "+f"(c[1]), "+f"(c[2]), "+f"(c[3])
        : "r"(a[0]), "r"(a[1]), "r"(a[2]), "r"(a[3]), "r"(b0), "r"(b1));
}

// ---------------------------------------------------------------------------
// Fused pre-pass: round x, w_qkv, w_out fp32 -> tf32 (rna) in ONE launch.
// ---------------------------------------------------------------------------
#define N4_X    (MTOT*CH/4)            // 1048576
#define N4_WQKV (3*CH*CH/4)            // 786432
#define N4_WOUT (CH*CH/4)              // 262144
#define N4_ALL  (N4_X + N4_WQKV + N4_WOUT)
__global__ void round_all(const float* __restrict__ x, const float* __restrict__ wq,
                          const float* __restrict__ wo) {
    int i = blockIdx.x * blockDim.x + threadIdx.x;
    int stride = gridDim.x * blockDim.x;
    for (; i < N4_ALL; i += stride) {
        const float* src; float* dst; int j;
        if (i < N4_X)                 { src = x;  dst = g_xr;    j = i; }
        else if (i < N4_X + N4_WQKV)  { src = wq; dst = g_wqkvr; j = i - N4_X; }
        else                          { src = wo; dst = g_woutr; j = i - N4_X - N4_WQKV; }
        float4 v = ((const float4*)src)[j];
        uint4 o = make_uint4(f2tf32(v.x), f2tf32(v.y), f2tf32(v.z), f2tf32(v.w));
        ((uint4*)dst)[j] = o;
    }
}

// ---------------------------------------------------------------------------
// QKV GEMM (tf32 mma.sync): D[128x96] = xr[128,1024] . w_qkvr^T slice
// Pre-rounded inputs, 3-stage cp.async pipeline (verified round-14 version).
// ---------------------------------------------------------------------------
#define QKV_SMEM (3*(128+96)*SK*4)   // 96768 B
__global__ __launch_bounds__(256, 2) void qkv_tc() {
    extern __shared__ __align__(16) float sm[];
    const uint32_t sbase = smem_u32(sm);
    uint32_t* sAu = (uint32_t*)sm;                 // 3 bufs x 128*SK
    uint32_t* sBu = (uint32_t*)sm + 3 * 128 * SK;  // 3 bufs x 96*SK
    const float* A = g_xr;
    const float* W = g_wqkvr;

    const int tid = threadIdx.x, warp = tid >> 5, lane = tid & 31;
    const int wm = warp >> 1, wn = warp & 1;
    const int g = lane >> 2, t = lane & 3;
    const int m0 = blockIdx.y * 128;
    const int bx = blockIdx.x;
    const int n0 = bx * 96;

    float acc[2][6][4];
#pragma unroll
    for (int i = 0; i < 2; ++i)
#pragma unroll
        for (int j = 0; j < 6; ++j)
#pragma unroll
            for (int q = 0; q < 4; ++q) acc[i][j][q] = 0.f;

    auto CPAB = [&](int c, int buf) {
        const int k0 = 32 * c;
        const uint32_t ao = sbase + (uint32_t)(buf * 128 * SK * 4);
        const uint32_t bo = sbase + (uint32_t)((3 * 128 + buf * 96) * SK * 4);
#pragma unroll
        for (int p = 0; p < 4; ++p) {
            int idx = tid + 256 * p, r = idx >> 3, q = idx & 7;
            cpa16(ao + (uint32_t)((r * SK + 4 * q) * 4),
                  A + (size_t)(m0 + r) * CH + k0 + 4 * q);
        }
#pragma unroll
        for (int p = 0; p < 3; ++p) {
            int idx = tid + 256 * p, r = idx >> 3, q = idx & 7;
            cpa16(bo + (uint32_t)((r * SK + 4 * q) * 4),
                  W + (size_t)(n0 + r) * CH + k0 + 4 * q);
        }
        CP_COMMIT();
    };

    CPAB(0, 0);
    CPAB(1, 1);

    for (int c = 0; c < 32; ++c) {
        const int buf = c % 3;
        if (c == 31) CP_WAIT0(); else CP_WAIT1();   // chunk c resident
        __syncthreads();    // all warps past chunk c-1 reads -> buf (c+2)%3 reusable
        if (c < 30) CPAB(c + 2, (c + 2) % 3);

        const uint32_t* bA = sAu + buf * 128 * SK;
        const uint32_t* bB = sBu + buf * 96 * SK;
#pragma unroll
        for (int s = 0; s < 4; ++s) {
            uint32_t afr[2][4];
#pragma unroll
            for (int mi = 0; mi < 2; ++mi) {
                const uint32_t* pa = bA + (wm * 32 + mi * 16 + g) * SK + s * 8 + t;
                afr[mi][0] = pa[0];
                afr[mi][1] = pa[8 * SK];
                afr[mi][2] = pa[4];
                afr[mi][3] = pa[8 * SK + 4];
            }
#pragma unroll
            for (int nj = 0; nj < 6; ++nj) {
                const uint32_t* pb = bB + (wn * 48 + nj * 8 + g) * SK + s * 8 + t;
                uint32_t b0 = pb[0], b1 = pb[4];
                mma8(acc[0][nj], afr[0], b0, b1);
                mma8(acc[1][nj], afr[1], b0, b1);
            }
        }
    }
    __syncthreads();   // all compute done before smem reuse for Ds

    float* Ds = sm;
#pragma unroll
    for (int mi = 0; mi < 2; ++mi)
#pragma unroll
        for (int nj = 0; nj < 6; ++nj) {
            int row = wm * 32 + mi * 16 + g;
            int col = wn * 48 + nj * 8 + 2 * t;
            *(float2*)(Ds + row * 100 + col) =
                make_float2(acc[mi][nj][0], acc[mi][nj][1]);
            *(float2*)(Ds + (row + 8) * 100 + col) =
                make_float2(acc[mi][nj][2], acc[mi][nj][3]);
        }
    __syncthreads();

    const int h = bx >> 1, hs0 = (bx & 1) * 32;
#pragma unroll
    for (int p = 0; p < 12; ++p) {
        int id = tid + 256 * p;
        int c4 = id & 7;
        int s = (id >> 3) % 3;
        int row = id / 24;
        int m = m0 + row;
        int bb = m >> 11, nn = m & 2047;
        float* dst = (s == 0) ? g_q : (s == 1) ? g_k : g_v;
        const float* Dr = Ds + row * 100 + 12 * c4 + s;
        float4 o;
        o.x = __uint_as_float(f2tf32(Dr[0]));
        o.y = __uint_as_float(f2tf32(Dr[3]));
        o.z = __uint_as_float(f2tf32(Dr[6]));
        o.w = __uint_as_float(f2tf32(Dr[9]));
        *(float4*)(dst + ((size_t)(bb * NH + h) * SEQ + nn) * HSZ + hs0 + 4 * c4) = o;
    }
}

// ---------------------------------------------------------------------------
// Flash attention (tf32 mma.sync): CTA = 128 query rows x one (b,h).
// K stride 68 (K-frag banks 4g+t: bijective), V stride 72 (transposed V-frag
// banks 8t+g: bijective -> conflicts eliminated), P stride 68.
// ex2.approx MUFU for all softmax exponentials.
// ---------------------------------------------------------------------------
#define KSTR 68
#define VSTR 72
#define VBASE (2*64*KSTR)                    // 8704 (words)
#define PBASE (VBASE + 2*64*VSTR)            // 17920 (words)
#define ATTN_SMEM ((PBASE + 128*KSTR) * 4)   // 106496 B
__global__ __launch_bounds__(256, 2) void attn_tc() {
    extern __shared__ __align__(16) float sm[];
    uint32_t* Ks = (uint32_t*)sm;               // [2][64][KSTR]
    uint32_t* Vs = (uint32_t*)sm + VBASE;       // [2][64][VSTR]
    uint32_t* Ps = (uint32_t*)sm + PBASE;       // [128][KSTR]
    const uint32_t sbase = smem_u32(sm);

    const int tid = threadIdx.x, warp = tid >> 5, lane = tid & 31;
    const int g = lane >> 2, t = lane & 3;
    const int bh = blockIdx.y;
    const int m0 = blockIdx.x * 128;
    const int wrow = warp * 16;
    const float* Qg = g_q + (size_t)bh * SEQ * HSZ;
    const float* Kg = g_k + (size_t)bh * SEQ * HSZ;
    const float* Vg = g_v + (size_t)bh * SEQ * HSZ;

    auto CPKV = [&](int n0, int b) {
#pragma unroll
        for (int p = 0; p < 4; ++p) {
            int idx = tid + 256 * p;
            int r = idx >> 4, q = idx & 15;
            cpa16(sbase + (uint32_t)(((b * 64 + r) * KSTR + 4 * q) * 4),
                  Kg + (size_t)(n0 + r) * HSZ + 4 * q);
            cpa16(sbase + (uint32_t)((VBASE + (b * 64 + r) * VSTR + 4 * q) * 4),
                  Vg + (size_t)(n0 + r) * HSZ + 4 * q);
        }
        CP_COMMIT();
    };

    // Hoist Q A-fragments into registers (log2e * 0.125 folded in)
    uint32_t qfr[8][4];
    {
        const float* q0 = Qg + (size_t)(m0 + wrow + g) * HSZ;
        const float* q1 = Qg + (size_t)(m0 + wrow + g + 8) * HSZ;
#pragma unroll
        for (int ks = 0; ks < 8; ++ks) {
            int c0 = ks * 8 + t, c1 = c0 + 4;
            qfr[ks][0] = f2tf32(q0[c0] * QSCALE);
            qfr[ks][1] = f2tf32(q1[c0] * QSCALE);
            qfr[ks][2] = f2tf32(q0[c1] * QSCALE);
            qfr[ks][3] = f2tf32(q1[c1] * QSCALE);
        }
    }

    CPKV(0, 0);

    float m_i[2] = {-1e30f, -1e30f};
    float l_i[2] = {0.f, 0.f};
    float acc_o[8][4];
#pragma unroll
    for (int nj = 0; nj < 8; ++nj)
#pragma unroll
        for (int q = 0; q < 4; ++q) acc_o[nj][q] = 0.f;

    for (int kt = 0; kt < 32; ++kt) {
        const int b = kt & 1;
        CP_WAIT0();
        __syncthreads();
        if (kt < 31) CPKV(64 * (kt + 1), b ^ 1);

        const uint32_t* Kb = Ks + b * 64 * KSTR;
        const uint32_t* Vb = Vs + b * 64 * VSTR;

        // S = Q.K^T  (warp: 16 x 64)
        float s[8][4];
#pragma unroll
        for (int nj = 0; nj < 8; ++nj)
#pragma unroll
            for (int q = 0; q < 4; ++q) s[nj][q] = 0.f;
#pragma unroll
        for (int ks = 0; ks < 8; ++ks) {
#pragma unroll
            for (int nj = 0; nj < 8; ++nj) {
                const uint32_t* pb = Kb + (nj * 8 + g) * KSTR + ks * 8 + t;
                mma8(s[nj], qfr[ks], pb[0], pb[4]);
            }
        }

        // Online softmax (log2 domain, MUFU ex2) on fragment rows (g, g+8)
        float mx0 = -1e30f, mx1 = -1e30f;
#pragma unroll
        for (int nj = 0; nj < 8; ++nj) {
            mx0 = fmaxf(mx0, fmaxf(s[nj][0], s[nj][1]));
            mx1 = fmaxf(mx1, fmaxf(s[nj][2], s[nj][3]));
        }
        mx0 = fmaxf(mx0, __shfl_xor_sync(0xffffffffu, mx0, 1));
        mx0 = fmaxf(mx0, __shfl_xor_sync(0xffffffffu, mx0, 2));
        mx1 = fmaxf(mx1, __shfl_xor_sync(0xffffffffu, mx1, 1));
        mx1 = fmaxf(mx1, __shfl_xor_sync(0xffffffffu, mx1, 2));
        float mn0 = fmaxf(m_i[0], mx0), mn1 = fmaxf(m_i[1], mx1);
        float a0 = ex2(m_i[0] - mn0), a1 = ex2(m_i[1] - mn1);
        m_i[0] = mn0; m_i[1] = mn1;
        float s0 = 0.f, s1 = 0.f;
#pragma unroll
        for (int nj = 0; nj < 8; ++nj) {
            s[nj][0] = ex2(s[nj][0] - mn0);
            s[nj][1] = ex2(s[nj][1] - mn0);
            s[nj][2] = ex2(s[nj][2] - mn1);
            s[nj][3] = ex2(s[nj][3] - mn1);
            s0 += s[nj][0] + s[nj][1];
            s1 += s[nj][2] + s[nj][3];
        }
        s0 += __shfl_xor_sync(0xffffffffu, s0, 1);
        s0 += __shfl_xor_sync(0xffffffffu, s0, 2);
        s1 += __shfl_xor_sync(0xffffffffu, s1, 1);
        s1 += __shfl_xor_sync(0xffffffffu, s1, 2);
        l_i[0] = l_i[0] * a0 + s0;
        l_i[1] = l_i[1] * a1 + s1;
#pragma unroll
        for (int nj = 0; nj < 8; ++nj) {
            acc_o[nj][0] *= a0; acc_o[nj][1] *= a0;
            acc_o[nj][2] *= a1; acc_o[nj][3] *= a1;
        }

        // Stage P (per-warp private rows -> warp-level sync only)
        uint32_t* pr0 = Ps + (wrow + g) * KSTR + 2 * t;
        uint32_t* pr1 = Ps + (wrow + g + 8) * KSTR + 2 * t;
#pragma unroll
        for (int nj = 0; nj < 8; ++nj) {
            uint2 w0 = make_uint2(f2tf32(s[nj][0]), f2tf32(s[nj][1]));
            uint2 w1 = make_uint2(f2tf32(s[nj][2]), f2tf32(s[nj][3]));
            *(uint2*)(pr0 + nj * 8) = w0;
            *(uint2*)(pr1 + nj * 8) = w1;
        }
        __syncwarp();

        // O += P.V  (V-frag banks 8t+g: conflict-free with stride 72)
#pragma unroll
        for (int ks = 0; ks < 8; ++ks) {
            uint32_t afr[4];
            const uint32_t* pa = Ps + (wrow + g) * KSTR + ks * 8 + t;
            afr[0] = pa[0];
            afr[1] = pa[8 * KSTR];
            afr[2] = pa[4];
            afr[3] = pa[8 * KSTR + 4];
            const uint32_t* vb0 = Vb + (ks * 8 + t) * VSTR + g;
            const uint32_t* vb1 = Vb + (ks * 8 + t + 4) * VSTR + g;
#pragma unroll
            for (int nj = 0; nj < 8; ++nj)
                mma8(acc_o[nj], afr, vb0[nj * 8], vb1[nj * 8]);
        }
        __syncwarp();
    }

    // Epilogue: normalize + write (B,N,C), pre-rounded to tf32 for proj
    const int b = bh >> 4, h = bh & 15;
    const float inv0 = 1.f / l_i[0], inv1 = 1.f / l_i[1];
    const int r0 = m0 + wrow + g, r1 = r0 + 8;
#pragma unroll
    for (int nj = 0; nj < 8; ++nj) {
        int col = h * HSZ + nj * 8 + 2 * t;
        float2 o0 = make_float2(__uint_as_float(f2tf32(acc_o[nj][0] * inv0)),
                                __uint_as_float(f2tf32(acc_o[nj][1] * inv0)));
        float2 o1 = make_float2(__uint_as_float(f2tf32(acc_o[nj][2] * inv1)),
                                __uint_as_float(f2tf32(acc_o[nj][3] * inv1)));
        *(float2*)(g_attn + ((size_t)(b * SEQ + r0)) * CH + col) = o0;
        *(float2*)(g_attn + ((size_t)(b * SEQ + r1)) * CH + col) = o1;
    }
}

// ---------------------------------------------------------------------------
// Output projection (tf32 mma.sync): out[128x128] = g_attn . w_outr^T + bias
// Pre-rounded inputs, 3-stage cp.async pipeline (verified round-14 version).
// ---------------------------------------------------------------------------
#define PROJ_SMEM (3*2*128*SK*4)   // 110592 B
__global__ __launch_bounds__(256, 2) void proj_tc(const float* __restrict__ bias,
                                                  float* __restrict__ out) {
    extern __shared__ __align__(16) float sm[];
    const uint32_t sbase = smem_u32(sm);
    uint32_t* sAu = (uint32_t*)sm;                 // 3 bufs x 128*SK
    uint32_t* sBu = (uint32_t*)sm + 3 * 128 * SK;  // 3 bufs x 128*SK
    const float* W = g_woutr;

    const int tid = threadIdx.x, warp = tid >> 5, lane = tid & 31;
    const int wm = warp >> 1, wn = warp & 1;
    const int g = lane >> 2, t = lane & 3;
    const int m0 = blockIdx.y * 128;
    const int n0 = blockIdx.x * 128;

    float acc[2][8][4];
#pragma unroll
    for (int i = 0; i < 2; ++i)
#pragma unroll
        for (int j = 0; j < 8; ++j)
#pragma unroll
            for (int q = 0; q < 4; ++q) acc[i][j][q] = 0.f;

    auto CPAB = [&](int c, int buf) {
        const int k0 = 32 * c;
        const uint32_t ao = sbase + (uint32_t)(buf * 128 * SK * 4);
        const uint32_t bo = sbase + (uint32_t)((3 + buf) * 128 * SK * 4);
#pragma unroll
        for (int p = 0; p < 4; ++p) {
            int idx = tid + 256 * p, r = idx >> 3, q = idx & 7;
            cpa16(ao + (uint32_t)((r * SK + 4 * q) * 4),
                  g_attn + (size_t)(m0 + r) * CH + k0 + 4 * q);
            cpa16(bo + (uint32_t)((r * SK + 4 * q) * 4),
                  W + (size_t)(n0 + r) * CH + k0 + 4 * q);
        }
        CP_COMMIT();
    };

    CPAB(0, 0);
    CPAB(1, 1);

    for (int c = 0; c < 32; ++c) {
        const int buf = c % 3;
        if (c == 31) CP_WAIT0(); else CP_WAIT1();
        __syncthreads();
        if (c < 30) CPAB(c + 2, (c + 2) % 3);

        const uint32_t* bA = sAu + buf * 128 * SK;
        const uint32_t* bB = sBu + buf * 128 * SK;
#pragma unroll
        for (int s = 0; s < 4; ++s) {
            uint32_t afr[2][4];
#pragma unroll
            for (int mi = 0; mi < 2; ++mi) {
                const uint32_t* pa = bA + (wm * 32 + mi * 16 + g) * SK + s * 8 + t;
                afr[mi][0] = pa[0];
                afr[mi][1] = pa[8 * SK];
                afr[mi][2] = pa[4];
                afr[mi][3] = pa[8 * SK + 4];
            }
#pragma unroll
            for (int nj = 0; nj < 8; ++nj) {
                const uint32_t* pb = bB + (wn * 64 + nj * 8 + g) * SK + s * 8 + t;
                uint32_t b0 = pb[0], b1 = pb[4];
                mma8(acc[0][nj], afr[0], b0, b1);
                mma8(acc[1][nj], afr[1], b0, b1);
            }
        }
    }

#pragma unroll
    for (int mi = 0; mi < 2; ++mi)
#pragma unroll
        for (int nj = 0; nj < 8; ++nj) {
            int row = m0 + wm * 32 + mi * 16 + g;
            int col = n0 + wn * 64 + nj * 8 + 2 * t;
            float b0 = __ldg(bias + col), b1 = __ldg(bias + col + 1);
            *(float2*)(out + (size_t)row * CH + col) =
                make_float2(acc[mi][nj][0] + b0, acc[mi][nj][1] + b1);
            *(float2*)(out + (size_t)(row + 8) * CH + col) =
                make_float2(acc[mi][nj][2] + b0, acc[mi][nj][3] + b1);
        }
}

extern "C" void kernel_launch(void* const* d_in, const int* in_sizes, int n_in,
                              void* d_out, int out_size) {
    const float* x     = (const float*)d_in[0];
    const float* w_qkv = (const float*)d_in[1];
    const float* w_out = (const float*)d_in[2];
    const float* b_out = (const float*)d_in[3];
    float* out = (float*)d_out;

    cudaFuncSetAttribute(qkv_tc, cudaFuncAttributeMaxDynamicSharedMemorySize, QKV_SMEM);
    cudaFuncSetAttribute(attn_tc, cudaFuncAttributeMaxDynamicSharedMemorySize, ATTN_SMEM);
    cudaFuncSetAttribute(proj_tc, cudaFuncAttributeMaxDynamicSharedMemorySize, PROJ_SMEM);

    round_all<<<2368, 256>>>(x, w_qkv, w_out);
    qkv_tc<<<dim3(32, 32), 256, QKV_SMEM>>>();
    attn_tc<<<dim3(SEQ / 128, BATCH * NH), 256, ATTN_SMEM>>>();
    proj_tc<<<dim3(CH / 128, MTOT / 128), 256, PROJ_SMEM>>>(b_out, out);
}